// round 6
// baseline (speedup 1.0000x reference)
#include <cuda_runtime.h>
#include <math.h>

#define NIMG 8
#define AANCH 15
#define WW 100
#define HW 10000
#define HWA 150000
#define PRE 2000
#define POST 1000
#define CAND 4096

// ---------------- device scratch (static, no runtime alloc) ----------------
__device__ float g_sc[NIMG][HWA];                                   // sigmoid scores (input layout)
__device__ __align__(16) float g_boxes[NIMG][2048][4];              // compacted valid boxes, score order
__device__ float g_scores[NIMG][2048];
__device__ int   g_cnt[NIMG];                                       // V = #valid per image
__device__ unsigned long long g_mask[NIMG][2048][32];               // suppression bitmask rows

__constant__ float c_sizes[5]  = {32.f, 64.f, 128.f, 256.f, 512.f};
__constant__ float c_ratios[3] = {0.5f, 1.f, 2.f};

// monotone float<->uint key (larger float <-> larger key)
__device__ __forceinline__ unsigned int fkey(float f) {
    unsigned int u = __float_as_uint(f);
    return (u & 0x80000000u) ? ~u : (u | 0x80000000u);
}
__device__ __forceinline__ float funkey(unsigned int k) {
    unsigned int u = (k & 0x80000000u) ? (k ^ 0x80000000u) : ~k;
    return __uint_as_float(u);
}

// ---------------- kernel 0: sigmoid (bit-matching XLA logistic expander) ----
__global__ void sig_kernel(const float* __restrict__ obj) {
    int t = blockIdx.x * blockDim.x + threadIdx.x;
    if (t < NIMG * HWA) {
        float x = obj[t];
        ((float*)g_sc)[t] = __fdiv_rn(1.0f, __fadd_rn(1.0f, expf(-x)));
    }
}

// ---------------- kernel A: per-image top-2000 select + decode + compact ----
__global__ __launch_bounds__(1024) void topk_decode_kernel(const float* __restrict__ deltas)
{
    const int n = blockIdx.x;
    const int tid = threadIdx.x;
    const float* sc = g_sc[n];
    const float* dl = deltas + (size_t)n * HWA * 4;

    __shared__ unsigned int hist[2048];
    __shared__ unsigned long long cand[CAND];
    __shared__ unsigned int s_above, s_T, s_nc, s_b1, s_b2;

    if (tid == 0) { s_above = 0; s_nc = 0; }

    // ========== level 1: 11-bit histogram (warp-aggregated atomics) ==========
    hist[tid] = 0; hist[tid + 1024] = 0;
    __syncthreads();
    for (int jb = 0; jb < HWA; jb += 1024) {          // uniform trip count
        int j = jb + tid;
        unsigned int b = 0xFFFFFFFFu;
        if (j < HWA) b = fkey(sc[j]) >> 21;
        unsigned int mk = __match_any_sync(0xFFFFFFFFu, b);
        if (b != 0xFFFFFFFFu && (tid & 31) == (__ffs(mk) - 1))
            atomicAdd(&hist[b], (unsigned)__popc(mk));
    }
    __syncthreads();
    // inclusive suffix scan over 2048 bins
    for (int off = 1; off < 2048; off <<= 1) {
        unsigned a0 = hist[tid]        + ((tid + off < 2048)        ? hist[tid + off]        : 0u);
        unsigned a1 = hist[tid + 1024] + ((tid + 1024 + off < 2048) ? hist[tid + 1024 + off] : 0u);
        __syncthreads();
        hist[tid] = a0; hist[tid + 1024] = a1;
        __syncthreads();
    }
    // pick bucket: S[b] >= PRE > S[b+1]
    {
        unsigned target = PRE;
        #pragma unroll
        for (int q = 0; q < 2; q++) {
            int idx = tid + q * 1024;
            unsigned s = hist[idx];
            unsigned snx = (idx < 2047) ? hist[idx + 1] : 0u;
            if (s >= target && snx < target) { s_b1 = (unsigned)idx; s_above = snx; }
        }
    }
    __syncthreads();
    const unsigned int b1 = s_b1;

    // ========== level 2: next 11 bits ==========
    hist[tid] = 0; hist[tid + 1024] = 0;
    __syncthreads();
    for (int j = tid; j < HWA; j += 1024) {
        unsigned int k = fkey(sc[j]);
        if ((k >> 21) == b1) atomicAdd(&hist[(k >> 10) & 0x7FFu], 1u);
    }
    __syncthreads();
    for (int off = 1; off < 2048; off <<= 1) {
        unsigned a0 = hist[tid]        + ((tid + off < 2048)        ? hist[tid + off]        : 0u);
        unsigned a1 = hist[tid + 1024] + ((tid + 1024 + off < 2048) ? hist[tid + 1024 + off] : 0u);
        __syncthreads();
        hist[tid] = a0; hist[tid + 1024] = a1;
        __syncthreads();
    }
    {
        unsigned target = PRE - s_above;
        unsigned abv = s_above;
        #pragma unroll
        for (int q = 0; q < 2; q++) {
            int idx = tid + q * 1024;
            unsigned s = hist[idx];
            unsigned snx = (idx < 2047) ? hist[idx + 1] : 0u;
            if (s >= target && snx < target) { s_b2 = (unsigned)idx; s_above = abv + snx; }
        }
    }
    __syncthreads();
    const unsigned int pfx = (b1 << 21) | (s_b2 << 10);

    // ========== level 3: last 10 bits -> exact threshold key ==========
    hist[tid] = 0; hist[tid + 1024] = 0;
    __syncthreads();
    for (int j = tid; j < HWA; j += 1024) {
        unsigned int k = fkey(sc[j]);
        if ((k & 0xFFFFFC00u) == pfx) atomicAdd(&hist[k & 0x3FFu], 1u);
    }
    __syncthreads();
    for (int off = 1; off < 2048; off <<= 1) {
        unsigned a0 = hist[tid]        + ((tid + off < 2048)        ? hist[tid + off]        : 0u);
        unsigned a1 = hist[tid + 1024] + ((tid + 1024 + off < 2048) ? hist[tid + 1024 + off] : 0u);
        __syncthreads();
        hist[tid] = a0; hist[tid + 1024] = a1;
        __syncthreads();
    }
    {
        unsigned target = PRE - s_above;
        #pragma unroll
        for (int q = 0; q < 2; q++) {
            int idx = tid + q * 1024;
            unsigned s = hist[idx];
            unsigned snx = (idx < 2047) ? hist[idx + 1] : 0u;
            if (s >= target && snx < target) s_T = pfx | (unsigned)idx;
        }
    }
    __syncthreads();
    const unsigned int T = s_T;

    // ---- gather candidates (key >= T). composite = key<<32 | ~refIdx ----
    for (int j = tid; j < HWA; j += 1024) {
        unsigned int k = fkey(sc[j]);
        if (k >= T) {
            unsigned int p = atomicAdd(&s_nc, 1u);
            if (p < CAND) {
                unsigned int i = (unsigned)((j % HW) * AANCH + j / HW);  // reference HWA index
                cand[p] = ((unsigned long long)k << 32) | (unsigned int)(~i);
            }
        }
    }
    __syncthreads();
    unsigned int nc = s_nc; if (nc > CAND) nc = CAND;
    for (unsigned int p = nc + tid; p < CAND; p += 1024) cand[p] = 0ull;
    __syncthreads();

    // ---- bitonic sort, descending composite (score desc, index asc) ----
    for (int len = 2; len <= CAND; len <<= 1) {
        for (int stride = len >> 1; stride > 0; stride >>= 1) {
            for (int v = tid; v < CAND / 2; v += 1024) {
                int pos = 2 * stride * (v / stride) + (v % stride);
                int par = pos + stride;
                unsigned long long a = cand[pos], b2 = cand[par];
                bool desc = ((pos & len) == 0);
                if (desc ? (a < b2) : (a > b2)) { cand[pos] = b2; cand[par] = a; }
            }
            __syncthreads();
        }
    }

    // ---- decode top PRE, clip, min-size filter ----
    float bxv[2][4]; float scv[2]; unsigned validq[2];
    #pragma unroll
    for (int q = 0; q < 2; q++) {
        int r = tid + q * 1024;
        validq[q] = 0;
        if (r < PRE) {
            unsigned long long c = cand[r];
            unsigned int k = (unsigned int)(c >> 32);
            unsigned int i = ~((unsigned int)c);
            scv[q] = funkey(k);                        // exact sigmoid bits
            int a = (int)(i % AANCH);
            int cell = (int)(i / AANCH);
            int x = cell % WW, y = cell / WW;
            int rIdx = a / 5, sIdx = a % 5;
            float hr = sqrtf(c_ratios[rIdx]);
            float wr = __fdiv_rn(1.0f, hr);
            float wss = __fmul_rn(wr, c_sizes[sIdx]);
            float hss = __fmul_rn(hr, c_sizes[sIdx]);
            float bx1 = rintf(-0.5f * wss), bx2 = rintf(0.5f * wss);
            float by1 = rintf(-0.5f * hss), by2 = rintf(0.5f * hss);
            float ax1 = x * 16.f + bx1, ax2 = x * 16.f + bx2;
            float ay1 = y * 16.f + by1, ay2 = y * 16.f + by2;
            float wa = ax2 - ax1, ha = ay2 - ay1;      // exact integers
            float cxa = ax1 + 0.5f * wa, cya = ay1 + 0.5f * ha;
            float ddx = dl[(a * 4 + 0) * HW + cell];
            float ddy = dl[(a * 4 + 1) * HW + cell];
            float ddw = fminf(dl[(a * 4 + 2) * HW + cell], 4.1351665567423563f);
            float ddh = fminf(dl[(a * 4 + 3) * HW + cell], 4.1351665567423563f);
            float cx = __fadd_rn(__fmul_rn(ddx, wa), cxa);
            float cy = __fadd_rn(__fmul_rn(ddy, ha), cya);
            float w  = __fmul_rn(expf(ddw), wa);
            float h  = __fmul_rn(expf(ddh), ha);
            float x1 = __fsub_rn(cx, __fmul_rn(0.5f, w));
            float y1 = __fsub_rn(cy, __fmul_rn(0.5f, h));
            float x2 = __fadd_rn(cx, __fmul_rn(0.5f, w));
            float y2 = __fadd_rn(cy, __fmul_rn(0.5f, h));
            x1 = fminf(fmaxf(x1, 0.f), 1600.f);
            y1 = fminf(fmaxf(y1, 0.f), 1600.f);
            x2 = fminf(fmaxf(x2, 0.f), 1600.f);
            y2 = fminf(fmaxf(y2, 0.f), 1600.f);
            bxv[q][0] = x1; bxv[q][1] = y1; bxv[q][2] = x2; bxv[q][3] = y2;
            validq[q] = (__fsub_rn(x2, x1) >= 1e-3f) && (__fsub_rn(y2, y1) >= 1e-3f);
        }
    }
    __syncthreads();
    // parallel prefix sum of valid flags (forward inclusive over 2048)
    hist[tid] = (tid < PRE) ? validq[0] : 0u;
    hist[tid + 1024] = (tid + 1024 < PRE) ? validq[1] : 0u;
    __syncthreads();
    for (int off = 1; off < 2048; off <<= 1) {
        unsigned a0 = hist[tid]        + ((tid >= off)        ? hist[tid - off]        : 0u);
        unsigned a1 = hist[tid + 1024] + ((tid + 1024 >= off) ? hist[tid + 1024 - off] : 0u);
        __syncthreads();
        hist[tid] = a0; hist[tid + 1024] = a1;
        __syncthreads();
    }
    if (tid == 0) g_cnt[n] = (int)hist[PRE - 1];
    #pragma unroll
    for (int q = 0; q < 2; q++) {
        int r = tid + q * 1024;
        if (r < PRE && validq[q]) {
            int p = (int)hist[r] - 1;
            g_boxes[n][p][0] = bxv[q][0];
            g_boxes[n][p][1] = bxv[q][1];
            g_boxes[n][p][2] = bxv[q][2];
            g_boxes[n][p][3] = bxv[q][3];
            g_scores[n][p]   = scv[q];
        }
    }
}

// ---------------- kernel B: 64x64-tiled IoU suppression bitmask -------------
__global__ void iou_kernel() {
    const int n = blockIdx.z, bi = blockIdx.y, bj = blockIdx.x;
    const int V = g_cnt[n];
    __shared__ float4 cb[64];
    const int j0 = bj * 64;
    const int t = threadIdx.x;
    {
        int j = j0 + t;
        float4 b = make_float4(0.f, 0.f, 0.f, 0.f);
        if (j < V) b = *reinterpret_cast<const float4*>(g_boxes[n][j]);
        cb[t] = b;
    }
    __syncthreads();
    const int i = bi * 64 + t;
    unsigned long long m = 0ull;
    if (i < V && j0 + 63 > i && j0 < V) {
        float4 bb = *reinterpret_cast<const float4*>(g_boxes[n][i]);
        float ai = __fmul_rn(__fsub_rn(bb.z, bb.x), __fsub_rn(bb.w, bb.y));
        int tmax = min(64, V - j0);
        for (int u = 0; u < tmax; u++) {
            int j = j0 + u;
            if (j <= i) continue;
            float4 cc = cb[u];
            float aj = __fmul_rn(__fsub_rn(cc.z, cc.x), __fsub_rn(cc.w, cc.y));
            float xx1 = fmaxf(bb.x, cc.x), yy1 = fmaxf(bb.y, cc.y);
            float xx2 = fminf(bb.z, cc.z), yy2 = fminf(bb.w, cc.w);
            float iw = fmaxf(__fsub_rn(xx2, xx1), 0.f);
            float ih = fmaxf(__fsub_rn(yy2, yy1), 0.f);
            float inter = __fmul_rn(iw, ih);
            float den = __fadd_rn(__fsub_rn(__fadd_rn(ai, aj), inter), 1e-6f);
            float iou = __fdiv_rn(inter, den);
            if (iou > 0.7f) m |= (1ull << u);
        }
    }
    g_mask[n][i][bj] = m;
}

// ---------------- kernel C: blocked greedy NMS reduce + output --------------
__global__ void nms_kernel(float* __restrict__ out) {
    const int n = blockIdx.x, lane = threadIdx.x;
    const int V = g_cnt[n];
    __shared__ unsigned long long diag[64];
    unsigned long long rem = 0ull;                      // lane l owns columns [64l, 64l+64)
    int outc = 0;
    float* po = out + (size_t)n * POST * 5;
    const int nblk = (V + 63) >> 6;                     // <= 32
    for (int w = 0; w < nblk; w++) {
        const int base = w << 6;
        const int lim = min(64, V - base);
        // cooperative diagonal-word load (rows base..base+63, column word w)
        diag[lane]      = g_mask[n][base + lane][w];
        diag[lane + 32] = g_mask[n][base + lane + 32][w];
        __syncwarp();
        // redundant serial decisions (identical in every lane, register-resident)
        unsigned long long remw = __shfl_sync(0xFFFFFFFFu, rem, w);
        unsigned long long keep = 0ull;
        for (int u = 0; u < lim; u++) {
            if (!((remw >> u) & 1ull)) {
                keep |= 1ull << u;
                remw |= diag[u];
            }
        }
        __syncwarp();
        // apply: branch-free OR of kept rows' full masks (high MLP)
        #pragma unroll 8
        for (int u = 0; u < 64; u++) {
            unsigned long long row = g_mask[n][base + u][lane];
            unsigned long long sel = 0ull - ((keep >> u) & 1ull);
            rem |= row & sel;
        }
        // emit kept rows in order
        unsigned long long kb = keep;
        while (kb && outc < POST) {
            int u = __ffsll(kb) - 1; kb &= kb - 1;
            int i = base + u;
            if (lane < 5) po[outc * 5 + lane] = (lane < 4) ? g_boxes[n][i][lane] : g_scores[n][i];
            outc++;
        }
        outc += __popcll(kb);
    }
    int oc = min(outc, POST);
    int remf = (POST - oc) * 5;
    float* pz = po + oc * 5;
    for (int t2 = lane; t2 < remf; t2 += 32) pz[t2] = 0.f;
}

// ---------------- launch ----------------------------------------------------
extern "C" void kernel_launch(void* const* d_in, const int* in_sizes, int n_in,
                              void* d_out, int out_size) {
    const float* obj = (const float*)d_in[0];
    const float* dl  = (const float*)d_in[1];
    if (in_sizes[0] != NIMG * HWA) { const float* t = obj; obj = dl; dl = t; }

    sig_kernel<<<(NIMG * HWA + 255) / 256, 256>>>(obj);
    topk_decode_kernel<<<NIMG, 1024>>>(dl);
    dim3 gb(32, 32, NIMG);
    iou_kernel<<<gb, 64>>>();
    nms_kernel<<<NIMG, 32>>>((float*)d_out);
}

// round 7
// speedup vs baseline: 2.0384x; 2.0384x over previous
#include <cuda_runtime.h>
#include <math.h>

#define NIMG 8
#define AANCH 15
#define WW 100
#define HW 10000
#define HWA 150000
#define PRE 2000
#define POST 1000
#define CAND 4096

// ---------------- device scratch (static, no runtime alloc) ----------------
__device__ float g_sc[NIMG][HWA];                                   // sigmoid scores (input layout)
__device__ __align__(16) float g_boxes[NIMG][2048][4];              // compacted valid boxes, score order
__device__ float g_scores[NIMG][2048];
__device__ int   g_cnt[NIMG];                                       // V = #valid per image
__device__ unsigned long long g_mask[NIMG][2048][32];               // suppression bitmask rows

__constant__ float c_sizes[5]  = {32.f, 64.f, 128.f, 256.f, 512.f};
__constant__ float c_ratios[3] = {0.5f, 1.f, 2.f};

// monotone float<->uint key (larger float <-> larger key)
__device__ __forceinline__ unsigned int fkey(float f) {
    unsigned int u = __float_as_uint(f);
    return (u & 0x80000000u) ? ~u : (u | 0x80000000u);
}
__device__ __forceinline__ float funkey(unsigned int k) {
    unsigned int u = (k & 0x80000000u) ? (k ^ 0x80000000u) : ~k;
    return __uint_as_float(u);
}

// ---------------- kernel 0: sigmoid (bit-matching XLA logistic expander) ----
__global__ void sig_kernel(const float* __restrict__ obj) {
    int t = blockIdx.x * blockDim.x + threadIdx.x;
    if (t < NIMG * HWA) {
        float x = obj[t];
        ((float*)g_sc)[t] = __fdiv_rn(1.0f, __fadd_rn(1.0f, expf(-x)));
    }
}

// ---------------- kernel A: per-image top-2000 select + decode + compact ----
__global__ __launch_bounds__(1024) void topk_decode_kernel(const float* __restrict__ deltas)
{
    const int n = blockIdx.x;
    const int tid = threadIdx.x;
    const float* sc = g_sc[n];
    const float* dl = deltas + (size_t)n * HWA * 4;

    __shared__ unsigned int hist[2048];
    __shared__ unsigned long long cand[CAND];
    __shared__ unsigned int s_above, s_T, s_nc, s_b1, s_b2;

    if (tid == 0) { s_above = 0; s_nc = 0; }

    // ========== level 1: 11-bit histogram (warp-aggregated atomics) ==========
    hist[tid] = 0; hist[tid + 1024] = 0;
    __syncthreads();
    for (int jb = 0; jb < HWA; jb += 1024) {          // uniform trip count
        int j = jb + tid;
        unsigned int b = 0xFFFFFFFFu;
        if (j < HWA) b = fkey(sc[j]) >> 21;
        unsigned int mk = __match_any_sync(0xFFFFFFFFu, b);
        if (b != 0xFFFFFFFFu && (tid & 31) == (__ffs(mk) - 1))
            atomicAdd(&hist[b], (unsigned)__popc(mk));
    }
    __syncthreads();
    // inclusive suffix scan over 2048 bins
    for (int off = 1; off < 2048; off <<= 1) {
        unsigned a0 = hist[tid]        + ((tid + off < 2048)        ? hist[tid + off]        : 0u);
        unsigned a1 = hist[tid + 1024] + ((tid + 1024 + off < 2048) ? hist[tid + 1024 + off] : 0u);
        __syncthreads();
        hist[tid] = a0; hist[tid + 1024] = a1;
        __syncthreads();
    }
    {
        unsigned target = PRE;
        #pragma unroll
        for (int q = 0; q < 2; q++) {
            int idx = tid + q * 1024;
            unsigned s = hist[idx];
            unsigned snx = (idx < 2047) ? hist[idx + 1] : 0u;
            if (s >= target && snx < target) { s_b1 = (unsigned)idx; s_above = snx; }
        }
    }
    __syncthreads();
    const unsigned int b1 = s_b1;

    // ========== level 2: next 11 bits ==========
    hist[tid] = 0; hist[tid + 1024] = 0;
    __syncthreads();
    for (int j = tid; j < HWA; j += 1024) {
        unsigned int k = fkey(sc[j]);
        if ((k >> 21) == b1) atomicAdd(&hist[(k >> 10) & 0x7FFu], 1u);
    }
    __syncthreads();
    for (int off = 1; off < 2048; off <<= 1) {
        unsigned a0 = hist[tid]        + ((tid + off < 2048)        ? hist[tid + off]        : 0u);
        unsigned a1 = hist[tid + 1024] + ((tid + 1024 + off < 2048) ? hist[tid + 1024 + off] : 0u);
        __syncthreads();
        hist[tid] = a0; hist[tid + 1024] = a1;
        __syncthreads();
    }
    {
        unsigned target = PRE - s_above;
        unsigned abv = s_above;
        #pragma unroll
        for (int q = 0; q < 2; q++) {
            int idx = tid + q * 1024;
            unsigned s = hist[idx];
            unsigned snx = (idx < 2047) ? hist[idx + 1] : 0u;
            if (s >= target && snx < target) { s_b2 = (unsigned)idx; s_above = abv + snx; }
        }
    }
    __syncthreads();
    const unsigned int pfx = (b1 << 21) | (s_b2 << 10);

    // ========== level 3: last 10 bits -> exact threshold key ==========
    hist[tid] = 0; hist[tid + 1024] = 0;
    __syncthreads();
    for (int j = tid; j < HWA; j += 1024) {
        unsigned int k = fkey(sc[j]);
        if ((k & 0xFFFFFC00u) == pfx) atomicAdd(&hist[k & 0x3FFu], 1u);
    }
    __syncthreads();
    for (int off = 1; off < 2048; off <<= 1) {
        unsigned a0 = hist[tid]        + ((tid + off < 2048)        ? hist[tid + off]        : 0u);
        unsigned a1 = hist[tid + 1024] + ((tid + 1024 + off < 2048) ? hist[tid + 1024 + off] : 0u);
        __syncthreads();
        hist[tid] = a0; hist[tid + 1024] = a1;
        __syncthreads();
    }
    {
        unsigned target = PRE - s_above;
        #pragma unroll
        for (int q = 0; q < 2; q++) {
            int idx = tid + q * 1024;
            unsigned s = hist[idx];
            unsigned snx = (idx < 2047) ? hist[idx + 1] : 0u;
            if (s >= target && snx < target) s_T = pfx | (unsigned)idx;
        }
    }
    __syncthreads();
    const unsigned int T = s_T;

    // ---- gather candidates (key >= T). composite = key<<32 | ~refIdx ----
    for (int j = tid; j < HWA; j += 1024) {
        unsigned int k = fkey(sc[j]);
        if (k >= T) {
            unsigned int p = atomicAdd(&s_nc, 1u);
            if (p < CAND) {
                unsigned int i = (unsigned)((j % HW) * AANCH + j / HW);  // reference HWA index
                cand[p] = ((unsigned long long)k << 32) | (unsigned int)(~i);
            }
        }
    }
    __syncthreads();
    unsigned int nc = s_nc; if (nc > CAND) nc = CAND;
    for (unsigned int p = nc + tid; p < CAND; p += 1024) cand[p] = 0ull;
    __syncthreads();

    // ---- bitonic sort, descending composite (score desc, index asc) ----
    for (int len = 2; len <= CAND; len <<= 1) {
        for (int stride = len >> 1; stride > 0; stride >>= 1) {
            for (int v = tid; v < CAND / 2; v += 1024) {
                int pos = 2 * stride * (v / stride) + (v % stride);
                int par = pos + stride;
                unsigned long long a = cand[pos], b2 = cand[par];
                bool desc = ((pos & len) == 0);
                if (desc ? (a < b2) : (a > b2)) { cand[pos] = b2; cand[par] = a; }
            }
            __syncthreads();
        }
    }

    // ---- decode top PRE, clip, min-size filter ----
    float bxv[2][4]; float scv[2]; unsigned validq[2];
    #pragma unroll
    for (int q = 0; q < 2; q++) {
        int r = tid + q * 1024;
        validq[q] = 0;
        if (r < PRE) {
            unsigned long long c = cand[r];
            unsigned int k = (unsigned int)(c >> 32);
            unsigned int i = ~((unsigned int)c);
            scv[q] = funkey(k);                        // exact sigmoid bits
            int a = (int)(i % AANCH);
            int cell = (int)(i / AANCH);
            int x = cell % WW, y = cell / WW;
            int rIdx = a / 5, sIdx = a % 5;
            float hr = sqrtf(c_ratios[rIdx]);
            float wr = __fdiv_rn(1.0f, hr);
            float wss = __fmul_rn(wr, c_sizes[sIdx]);
            float hss = __fmul_rn(hr, c_sizes[sIdx]);
            float bx1 = rintf(-0.5f * wss), bx2 = rintf(0.5f * wss);
            float by1 = rintf(-0.5f * hss), by2 = rintf(0.5f * hss);
            float ax1 = x * 16.f + bx1, ax2 = x * 16.f + bx2;
            float ay1 = y * 16.f + by1, ay2 = y * 16.f + by2;
            float wa = ax2 - ax1, ha = ay2 - ay1;      // exact integers
            float cxa = ax1 + 0.5f * wa, cya = ay1 + 0.5f * ha;
            float ddx = dl[(a * 4 + 0) * HW + cell];
            float ddy = dl[(a * 4 + 1) * HW + cell];
            float ddw = fminf(dl[(a * 4 + 2) * HW + cell], 4.1351665567423563f);
            float ddh = fminf(dl[(a * 4 + 3) * HW + cell], 4.1351665567423563f);
            float cx = __fadd_rn(__fmul_rn(ddx, wa), cxa);
            float cy = __fadd_rn(__fmul_rn(ddy, ha), cya);
            float w  = __fmul_rn(expf(ddw), wa);
            float h  = __fmul_rn(expf(ddh), ha);
            float x1 = __fsub_rn(cx, __fmul_rn(0.5f, w));
            float y1 = __fsub_rn(cy, __fmul_rn(0.5f, h));
            float x2 = __fadd_rn(cx, __fmul_rn(0.5f, w));
            float y2 = __fadd_rn(cy, __fmul_rn(0.5f, h));
            x1 = fminf(fmaxf(x1, 0.f), 1600.f);
            y1 = fminf(fmaxf(y1, 0.f), 1600.f);
            x2 = fminf(fmaxf(x2, 0.f), 1600.f);
            y2 = fminf(fmaxf(y2, 0.f), 1600.f);
            bxv[q][0] = x1; bxv[q][1] = y1; bxv[q][2] = x2; bxv[q][3] = y2;
            validq[q] = (__fsub_rn(x2, x1) >= 1e-3f) && (__fsub_rn(y2, y1) >= 1e-3f);
        }
    }
    __syncthreads();
    // parallel prefix sum of valid flags (forward inclusive over 2048)
    hist[tid] = (tid < PRE) ? validq[0] : 0u;
    hist[tid + 1024] = (tid + 1024 < PRE) ? validq[1] : 0u;
    __syncthreads();
    for (int off = 1; off < 2048; off <<= 1) {
        unsigned a0 = hist[tid]        + ((tid >= off)        ? hist[tid - off]        : 0u);
        unsigned a1 = hist[tid + 1024] + ((tid + 1024 >= off) ? hist[tid + 1024 - off] : 0u);
        __syncthreads();
        hist[tid] = a0; hist[tid + 1024] = a1;
        __syncthreads();
    }
    if (tid == 0) g_cnt[n] = (int)hist[PRE - 1];
    #pragma unroll
    for (int q = 0; q < 2; q++) {
        int r = tid + q * 1024;
        if (r < PRE && validq[q]) {
            int p = (int)hist[r] - 1;
            g_boxes[n][p][0] = bxv[q][0];
            g_boxes[n][p][1] = bxv[q][1];
            g_boxes[n][p][2] = bxv[q][2];
            g_boxes[n][p][3] = bxv[q][3];
            g_scores[n][p]   = scv[q];
        }
    }
}

// ---------------- kernel B: 64x64-tiled IoU suppression bitmask -------------
__global__ void iou_kernel() {
    const int n = blockIdx.z, bi = blockIdx.y, bj = blockIdx.x;
    const int V = g_cnt[n];
    __shared__ float4 cb[64];
    const int j0 = bj * 64;
    const int t = threadIdx.x;
    {
        int j = j0 + t;
        float4 b = make_float4(0.f, 0.f, 0.f, 0.f);
        if (j < V) b = *reinterpret_cast<const float4*>(g_boxes[n][j]);
        cb[t] = b;
    }
    __syncthreads();
    const int i = bi * 64 + t;
    unsigned long long m = 0ull;
    if (i < V && j0 + 63 > i && j0 < V) {
        float4 bb = *reinterpret_cast<const float4*>(g_boxes[n][i]);
        float ai = __fmul_rn(__fsub_rn(bb.z, bb.x), __fsub_rn(bb.w, bb.y));
        int tmax = min(64, V - j0);
        for (int u = 0; u < tmax; u++) {
            int j = j0 + u;
            if (j <= i) continue;
            float4 cc = cb[u];
            float aj = __fmul_rn(__fsub_rn(cc.z, cc.x), __fsub_rn(cc.w, cc.y));
            float xx1 = fmaxf(bb.x, cc.x), yy1 = fmaxf(bb.y, cc.y);
            float xx2 = fminf(bb.z, cc.z), yy2 = fminf(bb.w, cc.w);
            float iw = fmaxf(__fsub_rn(xx2, xx1), 0.f);
            float ih = fmaxf(__fsub_rn(yy2, yy1), 0.f);
            float inter = __fmul_rn(iw, ih);
            float den = __fadd_rn(__fsub_rn(__fadd_rn(ai, aj), inter), 1e-6f);
            float iou = __fdiv_rn(inter, den);
            if (iou > 0.7f) m |= (1ull << u);
        }
    }
    g_mask[n][i][bj] = m;
}

// ---------------- kernel C: greedy NMS, column-on-demand formulation --------
// At block w we only need sup_w = OR over previously-kept rows j of mask[j][w]
// (column words < w are never read again). sup_w is a fully parallel masked
// OR-gather; the only serial part is the 64-iteration in-register decision.
__global__ __launch_bounds__(256) void nms_kernel(float* __restrict__ out) {
    const int n = blockIdx.x;
    const int tid = threadIdx.x;
    const int lane = tid & 31, wid = tid >> 5;
    const int V = g_cnt[n];
    const int nblk = (V + 63) >> 6;                    // <= 32

    __shared__ unsigned long long skeep[32];
    __shared__ unsigned long long sdiag[64];
    __shared__ unsigned long long swarp[8];
    __shared__ int spfx[33];

    if (tid < 32) skeep[tid] = 0ull;
    __syncthreads();

    for (int w = 0; w < nblk; w++) {
        const int base = w << 6;
        // stage diagonal block (rows base..base+63, column word w)
        if (tid < 64) sdiag[tid] = g_mask[n][base + tid][w];
        // parallel masked OR-gather of column w over all prior rows
        unsigned long long part = 0ull;
        for (int r = tid; r < base; r += 256) {
            unsigned long long km = skeep[r >> 6];
            unsigned long long sel = 0ull - ((km >> (r & 63)) & 1ull);
            part |= g_mask[n][r][w] & sel;
        }
        #pragma unroll
        for (int o = 16; o > 0; o >>= 1)
            part |= __shfl_xor_sync(0xFFFFFFFFu, part, o);
        if (lane == 0) swarp[wid] = part;
        __syncthreads();

        if (wid == 0) {
            unsigned long long sup = swarp[0] | swarp[1] | swarp[2] | swarp[3]
                                   | swarp[4] | swarp[5] | swarp[6] | swarp[7];
            unsigned long long d[64];
            #pragma unroll
            for (int u = 0; u < 64; u++) d[u] = sdiag[u];
            unsigned long long remw = sup, keep = 0ull;
            #pragma unroll
            for (int u = 0; u < 64; u++) {
                // sel = ~0 if row not suppressed, else 0 (branch-free, no pred in chain)
                unsigned long long sel = ((remw >> u) & 1ull) - 1ull;
                keep |= sel & (1ull << u);
                remw |= d[u] & sel;
            }
            int lim = V - base;
            if (lim < 64) keep &= (1ull << lim) - 1ull;
            if (lane == 0) skeep[w] = keep;
        }
        __syncthreads();
    }

    // prefix popcounts of keep words
    if (tid == 0) {
        int c = 0;
        #pragma unroll
        for (int p = 0; p < 32; p++) { spfx[p] = c; c += __popcll(skeep[p]); }
        spfx[32] = c;
    }
    __syncthreads();

    float* po = out + (size_t)n * POST * 5;
    const int oc = min(spfx[32], POST);
    // parallel rank-scatter of kept rows
    for (int i = tid; i < V; i += 256) {
        unsigned long long km = skeep[i >> 6];
        if ((km >> (i & 63)) & 1ull) {
            int rank = spfx[i >> 6] + __popcll(km & ((1ull << (i & 63)) - 1ull));
            if (rank < POST) {
                float4 b = *reinterpret_cast<const float4*>(g_boxes[n][i]);
                po[rank * 5 + 0] = b.x;
                po[rank * 5 + 1] = b.y;
                po[rank * 5 + 2] = b.z;
                po[rank * 5 + 3] = b.w;
                po[rank * 5 + 4] = g_scores[n][i];
            }
        }
    }
    // zero-fill remaining rows
    for (int t = oc * 5 + tid; t < POST * 5; t += 256) po[t] = 0.f;
}

// ---------------- launch ----------------------------------------------------
extern "C" void kernel_launch(void* const* d_in, const int* in_sizes, int n_in,
                              void* d_out, int out_size) {
    const float* obj = (const float*)d_in[0];
    const float* dl  = (const float*)d_in[1];
    if (in_sizes[0] != NIMG * HWA) { const float* t = obj; obj = dl; dl = t; }

    sig_kernel<<<(NIMG * HWA + 255) / 256, 256>>>(obj);
    topk_decode_kernel<<<NIMG, 1024>>>(dl);
    dim3 gb(32, 32, NIMG);
    iou_kernel<<<gb, 64>>>();
    nms_kernel<<<NIMG, 256>>>((float*)d_out);
}

// round 8
// speedup vs baseline: 2.8916x; 1.4186x over previous
#include <cuda_runtime.h>
#include <math.h>

#define NIMG 8
#define AANCH 15
#define WW 100
#define HW 10000
#define HWA 150000
#define PRE 2000
#define POST 1000
#define CAND 4096

// ---------------- device scratch (static, no runtime alloc) ----------------
__device__ float g_sc[NIMG][HWA];                                   // sigmoid scores (input layout)
__device__ __align__(16) float g_boxes[NIMG][2048][4];              // compacted valid boxes, score order
__device__ float g_scores[NIMG][2048];
__device__ int   g_cnt[NIMG];                                       // V = #valid per image
__device__ unsigned long long g_mask[NIMG][2048][32];               // suppression bitmask rows

__constant__ float c_sizes[5]  = {32.f, 64.f, 128.f, 256.f, 512.f};
__constant__ float c_ratios[3] = {0.5f, 1.f, 2.f};

// monotone float<->uint key (larger float <-> larger key)
__device__ __forceinline__ unsigned int fkey(float f) {
    unsigned int u = __float_as_uint(f);
    return (u & 0x80000000u) ? ~u : (u | 0x80000000u);
}
__device__ __forceinline__ float funkey(unsigned int k) {
    unsigned int u = (k & 0x80000000u) ? (k ^ 0x80000000u) : ~k;
    return __uint_as_float(u);
}

// ---------------- kernel A: sigmoid + top-2000 select + decode + compact ----
__global__ __launch_bounds__(1024) void topk_decode_kernel(const float* __restrict__ obj,
                                                           const float* __restrict__ deltas)
{
    const int n = blockIdx.x;
    const int tid = threadIdx.x;
    const float* ob = obj + (size_t)n * HWA;
    float* sc = g_sc[n];
    const float* dl = deltas + (size_t)n * HWA * 4;

    __shared__ unsigned int hist[2048];
    __shared__ unsigned long long cand[CAND];
    __shared__ unsigned int s_above, s_nc, s_b1, s_b2;

    if (tid == 0) { s_above = 0; s_nc = 0; }

    // ========== pass 1: fused sigmoid + 11-bit histogram (warp-aggregated) ==========
    hist[tid] = 0; hist[tid + 1024] = 0;
    __syncthreads();
    for (int jb = 0; jb < HWA; jb += 1024) {          // uniform trip count (collective)
        int j = jb + tid;
        unsigned int b = 0xFFFFFFFFu;
        if (j < HWA) {
            float x = ob[j];
            float s = __fdiv_rn(1.0f, __fadd_rn(1.0f, expf(-x)));   // bit-match XLA logistic
            sc[j] = s;
            b = fkey(s) >> 21;
        }
        unsigned int mk = __match_any_sync(0xFFFFFFFFu, b);
        if (b != 0xFFFFFFFFu && (tid & 31) == (__ffs(mk) - 1))
            atomicAdd(&hist[b], (unsigned)__popc(mk));
    }
    __syncthreads();
    // inclusive suffix scan over 2048 bins
    for (int off = 1; off < 2048; off <<= 1) {
        unsigned a0 = hist[tid]        + ((tid + off < 2048)        ? hist[tid + off]        : 0u);
        unsigned a1 = hist[tid + 1024] + ((tid + 1024 + off < 2048) ? hist[tid + 1024 + off] : 0u);
        __syncthreads();
        hist[tid] = a0; hist[tid + 1024] = a1;
        __syncthreads();
    }
    {
        unsigned target = PRE;
        #pragma unroll
        for (int q = 0; q < 2; q++) {
            int idx = tid + q * 1024;
            unsigned s = hist[idx];
            unsigned snx = (idx < 2047) ? hist[idx + 1] : 0u;
            if (s >= target && snx < target) { s_b1 = (unsigned)idx; s_above = snx; }
        }
    }
    __syncthreads();
    const unsigned int b1 = s_b1;

    // ========== pass 2: next 11 bits ==========
    hist[tid] = 0; hist[tid + 1024] = 0;
    __syncthreads();
    for (int j = tid; j < HWA; j += 1024) {
        unsigned int k = fkey(sc[j]);
        if ((k >> 21) == b1) atomicAdd(&hist[(k >> 10) & 0x7FFu], 1u);
    }
    __syncthreads();
    for (int off = 1; off < 2048; off <<= 1) {
        unsigned a0 = hist[tid]        + ((tid + off < 2048)        ? hist[tid + off]        : 0u);
        unsigned a1 = hist[tid + 1024] + ((tid + 1024 + off < 2048) ? hist[tid + 1024 + off] : 0u);
        __syncthreads();
        hist[tid] = a0; hist[tid + 1024] = a1;
        __syncthreads();
    }
    {
        unsigned target = PRE - s_above;
        #pragma unroll
        for (int q = 0; q < 2; q++) {
            int idx = tid + q * 1024;
            unsigned s = hist[idx];
            unsigned snx = (idx < 2047) ? hist[idx + 1] : 0u;
            if (s >= target && snx < target) s_b2 = (unsigned)idx;
        }
    }
    __syncthreads();
    // threshold at level-2 bucket start: gathers a superset (~2000+eps <= CAND);
    // the exact top-2000 emerges from the sort.
    const unsigned int T = (b1 << 21) | (s_b2 << 10);

    // ---- gather candidates (key >= T). composite = key<<32 | ~refIdx ----
    for (int j = tid; j < HWA; j += 1024) {
        unsigned int k = fkey(sc[j]);
        if (k >= T) {
            unsigned int p = atomicAdd(&s_nc, 1u);
            if (p < CAND) {
                unsigned int i = (unsigned)((j % HW) * AANCH + j / HW);  // reference HWA index
                cand[p] = ((unsigned long long)k << 32) | (unsigned int)(~i);
            }
        }
    }
    __syncthreads();
    unsigned int nc = s_nc; if (nc > CAND) nc = CAND;
    for (unsigned int p = nc + tid; p < CAND; p += 1024) cand[p] = 0ull;
    __syncthreads();

    // ---- bitonic sort, descending composite (score desc, index asc) ----
    for (int len = 2; len <= CAND; len <<= 1) {
        for (int stride = len >> 1; stride > 0; stride >>= 1) {
            for (int v = tid; v < CAND / 2; v += 1024) {
                int low = v & (stride - 1);
                int pos = ((v ^ low) << 1) | low;      // 2*stride*(v/stride) + v%stride
                int par = pos + stride;
                unsigned long long a = cand[pos], b2 = cand[par];
                bool desc = ((pos & len) == 0);
                if (desc ? (a < b2) : (a > b2)) { cand[pos] = b2; cand[par] = a; }
            }
            __syncthreads();
        }
    }

    // ---- decode top PRE, clip, min-size filter ----
    float bxv[2][4]; float scv[2]; unsigned validq[2];
    #pragma unroll
    for (int q = 0; q < 2; q++) {
        int r = tid + q * 1024;
        validq[q] = 0;
        if (r < PRE) {
            unsigned long long c = cand[r];
            unsigned int k = (unsigned int)(c >> 32);
            unsigned int i = ~((unsigned int)c);
            scv[q] = funkey(k);                        // exact sigmoid bits
            int a = (int)(i % AANCH);
            int cell = (int)(i / AANCH);
            int x = cell % WW, y = cell / WW;
            int rIdx = a / 5, sIdx = a % 5;
            float hr = sqrtf(c_ratios[rIdx]);
            float wr = __fdiv_rn(1.0f, hr);
            float wss = __fmul_rn(wr, c_sizes[sIdx]);
            float hss = __fmul_rn(hr, c_sizes[sIdx]);
            float bx1 = rintf(-0.5f * wss), bx2 = rintf(0.5f * wss);
            float by1 = rintf(-0.5f * hss), by2 = rintf(0.5f * hss);
            float ax1 = x * 16.f + bx1, ax2 = x * 16.f + bx2;
            float ay1 = y * 16.f + by1, ay2 = y * 16.f + by2;
            float wa = ax2 - ax1, ha = ay2 - ay1;      // exact integers
            float cxa = ax1 + 0.5f * wa, cya = ay1 + 0.5f * ha;
            float ddx = dl[(a * 4 + 0) * HW + cell];
            float ddy = dl[(a * 4 + 1) * HW + cell];
            float ddw = fminf(dl[(a * 4 + 2) * HW + cell], 4.1351665567423563f);
            float ddh = fminf(dl[(a * 4 + 3) * HW + cell], 4.1351665567423563f);
            float cx = __fadd_rn(__fmul_rn(ddx, wa), cxa);
            float cy = __fadd_rn(__fmul_rn(ddy, ha), cya);
            float w  = __fmul_rn(expf(ddw), wa);
            float h  = __fmul_rn(expf(ddh), ha);
            float x1 = __fsub_rn(cx, __fmul_rn(0.5f, w));
            float y1 = __fsub_rn(cy, __fmul_rn(0.5f, h));
            float x2 = __fadd_rn(cx, __fmul_rn(0.5f, w));
            float y2 = __fadd_rn(cy, __fmul_rn(0.5f, h));
            x1 = fminf(fmaxf(x1, 0.f), 1600.f);
            y1 = fminf(fmaxf(y1, 0.f), 1600.f);
            x2 = fminf(fmaxf(x2, 0.f), 1600.f);
            y2 = fminf(fmaxf(y2, 0.f), 1600.f);
            bxv[q][0] = x1; bxv[q][1] = y1; bxv[q][2] = x2; bxv[q][3] = y2;
            validq[q] = (__fsub_rn(x2, x1) >= 1e-3f) && (__fsub_rn(y2, y1) >= 1e-3f);
        }
    }
    __syncthreads();
    // parallel prefix sum of valid flags (forward inclusive over 2048)
    hist[tid] = (tid < PRE) ? validq[0] : 0u;
    hist[tid + 1024] = (tid + 1024 < PRE) ? validq[1] : 0u;
    __syncthreads();
    for (int off = 1; off < 2048; off <<= 1) {
        unsigned a0 = hist[tid]        + ((tid >= off)        ? hist[tid - off]        : 0u);
        unsigned a1 = hist[tid + 1024] + ((tid + 1024 >= off) ? hist[tid + 1024 - off] : 0u);
        __syncthreads();
        hist[tid] = a0; hist[tid + 1024] = a1;
        __syncthreads();
    }
    if (tid == 0) g_cnt[n] = (int)hist[PRE - 1];
    #pragma unroll
    for (int q = 0; q < 2; q++) {
        int r = tid + q * 1024;
        if (r < PRE && validq[q]) {
            int p = (int)hist[r] - 1;
            g_boxes[n][p][0] = bxv[q][0];
            g_boxes[n][p][1] = bxv[q][1];
            g_boxes[n][p][2] = bxv[q][2];
            g_boxes[n][p][3] = bxv[q][3];
            g_scores[n][p]   = scv[q];
        }
    }
}

// ---------------- kernel B: IoU suppression bitmask (upper-tri words only) --
// nms only reads word w of row r when w >= r/64, so lower-triangle words are
// never written. 256 rows x 64-col-word per block; div-free IoU compare with
// exact-div fallback inside a narrow margin (decisions bit-identical).
__global__ __launch_bounds__(256) void iou_kernel() {
    const int n = blockIdx.z, bi = blockIdx.y, bj = blockIdx.x;
    if (bi * 4 > bj) return;                            // whole block below diagonal
    const int V = g_cnt[n];
    __shared__ float4 cb[64];
    __shared__ float ca[64];
    const int j0 = bj * 64;
    const int t = threadIdx.x;
    if (t < 64) {
        int j = j0 + t;
        float4 b = make_float4(0.f, 0.f, 0.f, 0.f);
        if (j < V) b = *reinterpret_cast<const float4*>(g_boxes[n][j]);
        cb[t] = b;
        ca[t] = __fmul_rn(__fsub_rn(b.z, b.x), __fsub_rn(b.w, b.y));
    }
    __syncthreads();
    const int i = bi * 256 + t;
    if (i >= 64 * (bj + 1)) return;                     // word below this row's diagonal
    unsigned long long m = 0ull;
    if (i < V && j0 < V && j0 + 63 > i) {
        float4 bb = *reinterpret_cast<const float4*>(g_boxes[n][i]);
        float ai = __fmul_rn(__fsub_rn(bb.z, bb.x), __fsub_rn(bb.w, bb.y));
        int tmax = min(64, V - j0);
        for (int u = 0; u < tmax; u++) {
            int j = j0 + u;
            if (j <= i) continue;
            float4 cc = cb[u];
            float xx1 = fmaxf(bb.x, cc.x), yy1 = fmaxf(bb.y, cc.y);
            float xx2 = fminf(bb.z, cc.z), yy2 = fminf(bb.w, cc.w);
            float iw = fmaxf(__fsub_rn(xx2, xx1), 0.f);
            float ih = fmaxf(__fsub_rn(yy2, yy1), 0.f);
            float inter = __fmul_rn(iw, ih);
            float den = __fadd_rn(__fsub_rn(__fadd_rn(ai, ca[u]), inter), 1e-6f);
            float thr = __fmul_rn(0.7f, den);
            bool sup;
            if (fabsf(__fsub_rn(inter, thr)) > 1e-4f * den)
                sup = inter > thr;                      // decision identical outside margin
            else
                sup = __fdiv_rn(inter, den) > 0.7f;     // exact fallback (rare)
            if (sup) m |= (1ull << u);
        }
    }
    g_mask[n][i][bj] = m;
}

// ---------------- kernel C: greedy NMS, column-on-demand + early exit -------
__global__ __launch_bounds__(256) void nms_kernel(float* __restrict__ out) {
    const int n = blockIdx.x;
    const int tid = threadIdx.x;
    const int lane = tid & 31, wid = tid >> 5;
    const int V = g_cnt[n];
    const int nblk = (V + 63) >> 6;                    // <= 32

    __shared__ unsigned long long skeep[32];
    __shared__ unsigned long long sdiag[64];
    __shared__ unsigned long long swarp[8];
    __shared__ int spfx[33];
    __shared__ int s_kc;

    if (tid < 32) skeep[tid] = 0ull;
    if (tid == 0) s_kc = 0;
    __syncthreads();

    for (int w = 0; w < nblk; w++) {
        const int base = w << 6;
        // stage diagonal block (rows base..base+63, column word w)
        if (tid < 64) sdiag[tid] = g_mask[n][base + tid][w];
        // parallel masked OR-gather of column w over all prior rows
        unsigned long long part = 0ull;
        for (int r = tid; r < base; r += 256) {
            unsigned long long km = skeep[r >> 6];
            unsigned long long sel = 0ull - ((km >> (r & 63)) & 1ull);
            part |= g_mask[n][r][w] & sel;
        }
        #pragma unroll
        for (int o = 16; o > 0; o >>= 1)
            part |= __shfl_xor_sync(0xFFFFFFFFu, part, o);
        if (lane == 0) swarp[wid] = part;
        __syncthreads();

        if (tid == 0) {
            unsigned long long remw = swarp[0] | swarp[1] | swarp[2] | swarp[3]
                                    | swarp[4] | swarp[5] | swarp[6] | swarp[7];
            unsigned long long keep = 0ull;
            // 12-cyc serial chain: SHL -> SAR(sign-bcast) -> LOP3.
            // sdiag loads are chain-independent (hoisted by ptxas).
            #pragma unroll
            for (int u = 0; u < 64; u++) {
                unsigned long long bc =
                    (unsigned long long)(((long long)(remw << (63 - u))) >> 63); // ~0 if suppressed
                keep |= ~bc & (1ull << u);                                       // off-chain
                remw |= sdiag[u] & ~bc;                                          // single LOP3
            }
            int lim = V - base;
            if (lim < 64) keep &= (1ull << lim) - 1ull;
            skeep[w] = keep;
            s_kc += __popcll(keep);
        }
        __syncthreads();
        if (s_kc >= POST) break;       // later decisions can't affect first 1000 kept
    }

    // prefix popcounts of keep words (unprocessed words are zero)
    if (tid == 0) {
        int c = 0;
        #pragma unroll
        for (int p = 0; p < 32; p++) { spfx[p] = c; c += __popcll(skeep[p]); }
        spfx[32] = c;
    }
    __syncthreads();

    float* po = out + (size_t)n * POST * 5;
    const int oc = min(spfx[32], POST);
    // parallel rank-scatter of kept rows
    for (int i = tid; i < V; i += 256) {
        unsigned long long km = skeep[i >> 6];
        if ((km >> (i & 63)) & 1ull) {
            int rank = spfx[i >> 6] + __popcll(km & ((1ull << (i & 63)) - 1ull));
            if (rank < POST) {
                float4 b = *reinterpret_cast<const float4*>(g_boxes[n][i]);
                po[rank * 5 + 0] = b.x;
                po[rank * 5 + 1] = b.y;
                po[rank * 5 + 2] = b.z;
                po[rank * 5 + 3] = b.w;
                po[rank * 5 + 4] = g_scores[n][i];
            }
        }
    }
    // zero-fill remaining rows
    for (int t = oc * 5 + tid; t < POST * 5; t += 256) po[t] = 0.f;
}

// ---------------- launch ----------------------------------------------------
extern "C" void kernel_launch(void* const* d_in, const int* in_sizes, int n_in,
                              void* d_out, int out_size) {
    const float* obj = (const float*)d_in[0];
    const float* dl  = (const float*)d_in[1];
    if (in_sizes[0] != NIMG * HWA) { const float* t = obj; obj = dl; dl = t; }

    topk_decode_kernel<<<NIMG, 1024>>>(obj, dl);
    dim3 gb(32, 8, NIMG);
    iou_kernel<<<gb, 256>>>();
    nms_kernel<<<NIMG, 256>>>((float*)d_out);
}

// round 11
// speedup vs baseline: 4.3311x; 1.4978x over previous
#include <cuda_runtime.h>
#include <math.h>

#define NIMG 8
#define AANCH 15
#define WW 100
#define HW 10000
#define HWA 150000
#define PRE 2000
#define POST 1000
#define GCAND 8192
#define SCAND 4096

// ---------------- device scratch (static, no runtime alloc) ----------------
__device__ float g_sc[NIMG][HWA];                                   // sigmoid scores (input layout)
__device__ __align__(16) float g_boxes[NIMG][2048][4];              // compacted valid boxes, score order
__device__ float g_scores[NIMG][2048];
__device__ int   g_cnt[NIMG];                                       // V = #valid per image
__device__ unsigned long long g_mask[NIMG][2048][32];               // suppression bitmask rows
__device__ unsigned int g_hist[NIMG][2048];                         // level-1 global histogram
__device__ unsigned int g_nc[NIMG];                                 // candidate counters
__device__ unsigned int g_T1[NIMG];                                 // coarse thresholds
__device__ unsigned long long g_cand[NIMG][GCAND];                  // coarse candidate supersets

__constant__ float c_sizes[5]  = {32.f, 64.f, 128.f, 256.f, 512.f};
__constant__ float c_ratios[3] = {0.5f, 1.f, 2.f};

// monotone float<->uint key (larger float <-> larger key)
__device__ __forceinline__ unsigned int fkey(float f) {
    unsigned int u = __float_as_uint(f);
    return (u & 0x80000000u) ? ~u : (u | 0x80000000u);
}
__device__ __forceinline__ float funkey(unsigned int k) {
    unsigned int u = (k & 0x80000000u) ? (k ^ 0x80000000u) : ~k;
    return __uint_as_float(u);
}

// ---------------- kernel Z: zero counters/histograms ------------------------
__global__ void zero_kernel() {
    int idx = blockIdx.x * 1024 + threadIdx.x;
    if (idx < NIMG * 2048) ((unsigned int*)g_hist)[idx] = 0u;
    if (idx < NIMG) g_nc[idx] = 0u;
}

// ---------------- kernel 1: fused sigmoid + level-1 histogram (multi-CTA) ---
__global__ __launch_bounds__(256) void hist_kernel(const float* __restrict__ obj) {
    const int n = blockIdx.y;
    const int base = blockIdx.x * 4096;
    const float* ob = obj + (size_t)n * HWA;
    float* sc = g_sc[n];
    #pragma unroll 4
    for (int it = 0; it < 16; it++) {
        int j = base + it * 256 + threadIdx.x;
        unsigned int b = 0xFFFFFFFFu;
        if (j < HWA) {
            float x = ob[j];
            float s = __fdiv_rn(1.0f, __fadd_rn(1.0f, expf(-x)));   // bit-match XLA logistic
            sc[j] = s;
            b = fkey(s) >> 21;
        }
        unsigned int mk = __match_any_sync(0xFFFFFFFFu, b);
        if (b != 0xFFFFFFFFu && (threadIdx.x & 31) == (__ffs(mk) - 1))
            atomicAdd(&g_hist[n][b], (unsigned)__popc(mk));
    }
}

// ---------------- kernel 2: pick coarse threshold T1 = b1<<21 ---------------
__global__ __launch_bounds__(1024) void pick_kernel() {
    const int n = blockIdx.x, tid = threadIdx.x;
    __shared__ unsigned int hist[2048];
    __shared__ unsigned int s_b1;
    hist[tid] = g_hist[n][tid];
    hist[tid + 1024] = g_hist[n][tid + 1024];
    __syncthreads();
    for (int off = 1; off < 2048; off <<= 1) {
        unsigned a0 = hist[tid]        + ((tid + off < 2048)        ? hist[tid + off]        : 0u);
        unsigned a1 = hist[tid + 1024] + ((tid + 1024 + off < 2048) ? hist[tid + 1024 + off] : 0u);
        __syncthreads();
        hist[tid] = a0; hist[tid + 1024] = a1;
        __syncthreads();
    }
    #pragma unroll
    for (int q = 0; q < 2; q++) {
        int idx = tid + q * 1024;
        unsigned s = hist[idx];
        unsigned snx = (idx < 2047) ? hist[idx + 1] : 0u;
        if (s >= PRE && snx < PRE) s_b1 = (unsigned)idx;
    }
    __syncthreads();
    if (tid == 0) g_T1[n] = s_b1 << 21;
}

// ---------------- kernel 3: multi-CTA gather of coarse superset -------------
__global__ __launch_bounds__(256) void gather_kernel() {
    const int n = blockIdx.y;
    const int base = blockIdx.x * 4096;
    const float* sc = g_sc[n];
    const unsigned int T = g_T1[n];
    const int lane = threadIdx.x & 31;
    #pragma unroll 4
    for (int it = 0; it < 16; it++) {
        int j = base + it * 256 + threadIdx.x;
        bool hit = false; unsigned int k = 0;
        if (j < HWA) { k = fkey(sc[j]); hit = (k >= T); }
        unsigned int bal = __ballot_sync(0xFFFFFFFFu, hit);
        if (!bal) continue;                               // uniform across warp
        unsigned int pos = 0;
        if (lane == 0) pos = atomicAdd(&g_nc[n], (unsigned)__popc(bal));
        pos = __shfl_sync(0xFFFFFFFFu, pos, 0);
        if (hit) {
            unsigned int p = pos + __popc(bal & ((1u << lane) - 1u));
            if (p < GCAND) {
                unsigned int i = (unsigned)((j % HW) * AANCH + j / HW);  // reference HWA index
                g_cand[n][p] = ((unsigned long long)k << 32) | (unsigned int)(~i);
            }
        }
    }
}

// ---------------- kernel 4: refine threshold + sort + decode + compact ------
__global__ __launch_bounds__(1024) void sortdecode_kernel(const float* __restrict__ deltas)
{
    const int n = blockIdx.x;
    const int tid = threadIdx.x;
    const float* dl = deltas + (size_t)n * HWA * 4;

    __shared__ unsigned int hist[2048];
    __shared__ unsigned long long cand[SCAND];
    __shared__ unsigned int s_b2, s_nc2;

    const unsigned int T1 = g_T1[n];
    unsigned int nc = g_nc[n]; if (nc > GCAND) nc = GCAND;
    if (tid == 0) s_nc2 = 0;
    hist[tid] = 0; hist[tid + 1024] = 0;
    __syncthreads();

    // refine histogram over next 11 key bits (bins >=2048 capped: all above b1)
    for (unsigned int p = tid; p < nc; p += 1024) {
        unsigned int k = (unsigned int)(g_cand[n][p] >> 32);
        unsigned int bin = min((k - T1) >> 10, 2047u);
        atomicAdd(&hist[bin], 1u);
    }
    __syncthreads();
    for (int off = 1; off < 2048; off <<= 1) {
        unsigned a0 = hist[tid]        + ((tid + off < 2048)        ? hist[tid + off]        : 0u);
        unsigned a1 = hist[tid + 1024] + ((tid + 1024 + off < 2048) ? hist[tid + 1024 + off] : 0u);
        __syncthreads();
        hist[tid] = a0; hist[tid + 1024] = a1;
        __syncthreads();
    }
    #pragma unroll
    for (int q = 0; q < 2; q++) {
        int idx = tid + q * 1024;
        unsigned s = hist[idx];
        unsigned snx = (idx < 2047) ? hist[idx + 1] : 0u;
        if (s >= PRE && snx < PRE) s_b2 = (unsigned)idx;    // T2 == R8's level-2 threshold
    }
    __syncthreads();
    const unsigned int b2 = s_b2;

    // gather refined set into shared (count in [2000, 2000+bin) — usually ~2000)
    for (unsigned int p = tid; p < nc; p += 1024) {
        unsigned long long c = g_cand[n][p];
        unsigned int k = (unsigned int)(c >> 32);
        unsigned int bin = min((k - T1) >> 10, 2047u);
        if (bin >= b2) {
            unsigned int q = atomicAdd(&s_nc2, 1u);
            if (q < SCAND) cand[q] = c;
        }
    }
    __syncthreads();
    unsigned int nc2 = s_nc2; if (nc2 > SCAND) nc2 = SCAND;
    const int ssz = (nc2 <= 2048) ? 2048 : SCAND;           // usually 2048: cheaper sort
    for (unsigned int p = nc2 + tid; p < (unsigned)ssz; p += 1024) cand[p] = 0ull;
    __syncthreads();

    // bitonic sort, descending composite (score desc, index asc)
    for (int len = 2; len <= ssz; len <<= 1) {
        for (int stride = len >> 1; stride > 0; stride >>= 1) {
            for (int v = tid; v < ssz / 2; v += 1024) {
                int low = v & (stride - 1);
                int pos = ((v ^ low) << 1) | low;
                int par = pos + stride;
                unsigned long long a = cand[pos], b = cand[par];
                bool desc = ((pos & len) == 0);
                if (desc ? (a < b) : (a > b)) { cand[pos] = b; cand[par] = a; }
            }
            __syncthreads();
        }
    }

    // decode top PRE, clip, min-size filter
    float bxv[2][4]; float scv[2]; unsigned validq[2];
    #pragma unroll
    for (int q = 0; q < 2; q++) {
        int r = tid + q * 1024;
        validq[q] = 0;
        if (r < PRE) {
            unsigned long long c = cand[r];
            unsigned int k = (unsigned int)(c >> 32);
            unsigned int i = ~((unsigned int)c);
            scv[q] = funkey(k);                        // exact sigmoid bits
            int a = (int)(i % AANCH);
            int cell = (int)(i / AANCH);
            int x = cell % WW, y = cell / WW;
            int rIdx = a / 5, sIdx = a % 5;
            float hr = sqrtf(c_ratios[rIdx]);
            float wr = __fdiv_rn(1.0f, hr);
            float wss = __fmul_rn(wr, c_sizes[sIdx]);
            float hss = __fmul_rn(hr, c_sizes[sIdx]);
            float bx1 = rintf(-0.5f * wss), bx2 = rintf(0.5f * wss);
            float by1 = rintf(-0.5f * hss), by2 = rintf(0.5f * hss);
            float ax1 = x * 16.f + bx1, ax2 = x * 16.f + bx2;
            float ay1 = y * 16.f + by1, ay2 = y * 16.f + by2;
            float wa = ax2 - ax1, ha = ay2 - ay1;      // exact integers
            float cxa = ax1 + 0.5f * wa, cya = ay1 + 0.5f * ha;
            float ddx = dl[(a * 4 + 0) * HW + cell];
            float ddy = dl[(a * 4 + 1) * HW + cell];
            float ddw = fminf(dl[(a * 4 + 2) * HW + cell], 4.1351665567423563f);
            float ddh = fminf(dl[(a * 4 + 3) * HW + cell], 4.1351665567423563f);
            float cx = __fadd_rn(__fmul_rn(ddx, wa), cxa);
            float cy = __fadd_rn(__fmul_rn(ddy, ha), cya);
            float w  = __fmul_rn(expf(ddw), wa);
            float h  = __fmul_rn(expf(ddh), ha);
            float x1 = __fsub_rn(cx, __fmul_rn(0.5f, w));
            float y1 = __fsub_rn(cy, __fmul_rn(0.5f, h));
            float x2 = __fadd_rn(cx, __fmul_rn(0.5f, w));
            float y2 = __fadd_rn(cy, __fmul_rn(0.5f, h));
            x1 = fminf(fmaxf(x1, 0.f), 1600.f);
            y1 = fminf(fmaxf(y1, 0.f), 1600.f);
            x2 = fminf(fmaxf(x2, 0.f), 1600.f);
            y2 = fminf(fmaxf(y2, 0.f), 1600.f);
            bxv[q][0] = x1; bxv[q][1] = y1; bxv[q][2] = x2; bxv[q][3] = y2;
            validq[q] = (__fsub_rn(x2, x1) >= 1e-3f) && (__fsub_rn(y2, y1) >= 1e-3f);
        }
    }
    __syncthreads();
    // parallel prefix sum of valid flags (forward inclusive over 2048)
    hist[tid] = (tid < PRE) ? validq[0] : 0u;
    hist[tid + 1024] = (tid + 1024 < PRE) ? validq[1] : 0u;
    __syncthreads();
    for (int off = 1; off < 2048; off <<= 1) {
        unsigned a0 = hist[tid]        + ((tid >= off)        ? hist[tid - off]        : 0u);
        unsigned a1 = hist[tid + 1024] + ((tid + 1024 >= off) ? hist[tid + 1024 - off] : 0u);
        __syncthreads();
        hist[tid] = a0; hist[tid + 1024] = a1;
        __syncthreads();
    }
    if (tid == 0) g_cnt[n] = (int)hist[PRE - 1];
    #pragma unroll
    for (int q = 0; q < 2; q++) {
        int r = tid + q * 1024;
        if (r < PRE && validq[q]) {
            int p = (int)hist[r] - 1;
            g_boxes[n][p][0] = bxv[q][0];
            g_boxes[n][p][1] = bxv[q][1];
            g_boxes[n][p][2] = bxv[q][2];
            g_boxes[n][p][3] = bxv[q][3];
            g_scores[n][p]   = scv[q];
        }
    }
}

// ---------------- kernel B: IoU suppression bitmask (upper-tri words only) --
__global__ __launch_bounds__(256) void iou_kernel() {
    const int n = blockIdx.z, bi = blockIdx.y, bj = blockIdx.x;
    if (bi * 4 > bj) return;                            // whole block below diagonal
    const int V = g_cnt[n];
    __shared__ float4 cb[64];
    __shared__ float ca[64];
    const int j0 = bj * 64;
    const int t = threadIdx.x;
    if (t < 64) {
        int j = j0 + t;
        float4 b = make_float4(0.f, 0.f, 0.f, 0.f);
        if (j < V) b = *reinterpret_cast<const float4*>(g_boxes[n][j]);
        cb[t] = b;
        ca[t] = __fmul_rn(__fsub_rn(b.z, b.x), __fsub_rn(b.w, b.y));
    }
    __syncthreads();
    const int i = bi * 256 + t;
    if (i >= 64 * (bj + 1)) return;                     // word below this row's diagonal
    unsigned long long m = 0ull;
    if (i < V && j0 < V && j0 + 63 > i) {
        float4 bb = *reinterpret_cast<const float4*>(g_boxes[n][i]);
        float ai = __fmul_rn(__fsub_rn(bb.z, bb.x), __fsub_rn(bb.w, bb.y));
        int tmax = min(64, V - j0);
        for (int u = 0; u < tmax; u++) {
            int j = j0 + u;
            if (j <= i) continue;
            float4 cc = cb[u];
            float xx1 = fmaxf(bb.x, cc.x), yy1 = fmaxf(bb.y, cc.y);
            float xx2 = fminf(bb.z, cc.z), yy2 = fminf(bb.w, cc.w);
            float iw = fmaxf(__fsub_rn(xx2, xx1), 0.f);
            float ih = fmaxf(__fsub_rn(yy2, yy1), 0.f);
            float inter = __fmul_rn(iw, ih);
            float den = __fadd_rn(__fsub_rn(__fadd_rn(ai, ca[u]), inter), 1e-6f);
            float thr = __fmul_rn(0.7f, den);
            bool sup;
            if (fabsf(__fsub_rn(inter, thr)) > 1e-4f * den)
                sup = inter > thr;                      // decision identical outside margin
            else
                sup = __fdiv_rn(inter, den) > 0.7f;     // exact fallback (rare)
            if (sup) m |= (1ull << u);
        }
    }
    g_mask[n][i][bj] = m;
}

// ---------------- kernel C: greedy NMS, column-on-demand + early exit -------
__global__ __launch_bounds__(256) void nms_kernel(float* __restrict__ out) {
    const int n = blockIdx.x;
    const int tid = threadIdx.x;
    const int lane = tid & 31, wid = tid >> 5;
    const int V = g_cnt[n];
    const int nblk = (V + 63) >> 6;                    // <= 32

    __shared__ unsigned long long skeep[32];
    __shared__ unsigned long long sdiag[64];
    __shared__ unsigned long long swarp[8];
    __shared__ int spfx[33];
    __shared__ int s_kc;

    if (tid < 32) skeep[tid] = 0ull;
    if (tid == 0) s_kc = 0;
    __syncthreads();

    for (int w = 0; w < nblk; w++) {
        const int base = w << 6;
        if (tid < 64) sdiag[tid] = g_mask[n][base + tid][w];
        unsigned long long part = 0ull;
        for (int r = tid; r < base; r += 256) {
            unsigned long long km = skeep[r >> 6];
            unsigned long long sel = 0ull - ((km >> (r & 63)) & 1ull);
            part |= g_mask[n][r][w] & sel;
        }
        #pragma unroll
        for (int o = 16; o > 0; o >>= 1)
            part |= __shfl_xor_sync(0xFFFFFFFFu, part, o);
        if (lane == 0) swarp[wid] = part;
        __syncthreads();

        if (tid == 0) {
            unsigned long long remw = swarp[0] | swarp[1] | swarp[2] | swarp[3]
                                    | swarp[4] | swarp[5] | swarp[6] | swarp[7];
            unsigned long long keep = 0ull;
            #pragma unroll
            for (int u = 0; u < 64; u++) {
                unsigned long long bc =
                    (unsigned long long)(((long long)(remw << (63 - u))) >> 63);
                keep |= ~bc & (1ull << u);
                remw |= sdiag[u] & ~bc;
            }
            int lim = V - base;
            if (lim < 64) keep &= (1ull << lim) - 1ull;
            skeep[w] = keep;
            s_kc += __popcll(keep);
        }
        __syncthreads();
        if (s_kc >= POST) break;
    }

    if (tid == 0) {
        int c = 0;
        #pragma unroll
        for (int p = 0; p < 32; p++) { spfx[p] = c; c += __popcll(skeep[p]); }
        spfx[32] = c;
    }
    __syncthreads();

    float* po = out + (size_t)n * POST * 5;
    const int oc = min(spfx[32], POST);
    for (int i = tid; i < V; i += 256) {
        unsigned long long km = skeep[i >> 6];
        if ((km >> (i & 63)) & 1ull) {
            int rank = spfx[i >> 6] + __popcll(km & ((1ull << (i & 63)) - 1ull));
            if (rank < POST) {
                float4 b = *reinterpret_cast<const float4*>(g_boxes[n][i]);
                po[rank * 5 + 0] = b.x;
                po[rank * 5 + 1] = b.y;
                po[rank * 5 + 2] = b.z;
                po[rank * 5 + 3] = b.w;
                po[rank * 5 + 4] = g_scores[n][i];
            }
        }
    }
    for (int t = oc * 5 + tid; t < POST * 5; t += 256) po[t] = 0.f;
}

// ---------------- launch ----------------------------------------------------
extern "C" void kernel_launch(void* const* d_in, const int* in_sizes, int n_in,
                              void* d_out, int out_size) {
    const float* obj = (const float*)d_in[0];
    const float* dl  = (const float*)d_in[1];
    if (in_sizes[0] != NIMG * HWA) { const float* t = obj; obj = dl; dl = t; }

    zero_kernel<<<16, 1024>>>();
    dim3 gh(37, NIMG);
    hist_kernel<<<gh, 256>>>(obj);
    pick_kernel<<<NIMG, 1024>>>();
    gather_kernel<<<gh, 256>>>();
    sortdecode_kernel<<<NIMG, 1024>>>(dl);
    dim3 gb(32, 8, NIMG);
    iou_kernel<<<gb, 256>>>();
    nms_kernel<<<NIMG, 256>>>((float*)d_out);
}

// round 13
// speedup vs baseline: 4.7196x; 1.0897x over previous
#include <cuda_runtime.h>
#include <math.h>

#define NIMG 8
#define AANCH 15
#define WW 100
#define HW 10000
#define HWA 150000
#define NF4 37500
#define PRE 2000
#define POST 1000
#define GCAND 8192
#define SCAND 4096
#define STATIC_KEY 0xBFD9999Au   /* fkey(1.7f): static logit prefilter */

// ---------------- device scratch (static, no runtime alloc) ----------------
__device__ __align__(16) float g_boxes[NIMG][2048][4];              // compacted valid boxes, score order
__device__ float g_scores[NIMG][2048];
__device__ int   g_cnt[NIMG];                                       // V = #valid per image
__device__ unsigned long long g_mask[NIMG][2048][32];               // suppression bitmask rows
__device__ unsigned int g_hist[NIMG][2048];                         // level-1 logit-key histogram (self-reset)
__device__ unsigned int g_pcnt[NIMG];                               // prefilter counters (self-reset)
__device__ unsigned int g_T1[NIMG];                                 // coarse thresholds (logit-key space)
__device__ unsigned long long g_pre[NIMG][GCAND];                   // prefilter list: xkey<<32 | ~refIdx

__constant__ float c_sizes[5]  = {32.f, 64.f, 128.f, 256.f, 512.f};
__constant__ float c_ratios[3] = {0.5f, 1.f, 2.f};

// monotone float<->uint key (larger float <-> larger key)
__device__ __forceinline__ unsigned int fkey(float f) {
    unsigned int u = __float_as_uint(f);
    return (u & 0x80000000u) ? ~u : (u | 0x80000000u);
}
__device__ __forceinline__ float funkey(unsigned int k) {
    unsigned int u = (k & 0x80000000u) ? (k ^ 0x80000000u) : ~k;
    return __uint_as_float(u);
}
__device__ __forceinline__ unsigned int refidx(int j) {             // input-layout j -> reference HWA index
    return (unsigned)((j % HW) * AANCH + j / HW);
}

// ---- kernel 1: logit-key histogram + static prefilter append (one pass) ----
__global__ __launch_bounds__(256) void hist_kernel(const float* __restrict__ obj) {
    const int n = blockIdx.y;
    const int lane = threadIdx.x & 31;
    const float4* ob4 = (const float4*)(obj + (size_t)n * HWA);
    unsigned int key[4];
    #pragma unroll
    for (int it = 0; it < 4; it++) {
        int v = blockIdx.x * 1024 + it * 256 + threadIdx.x;
        bool inb = v < NF4;
        float4 xv = make_float4(0.f, 0.f, 0.f, 0.f);
        if (inb) xv = ob4[v];
        key[0] = fkey(xv.x); key[1] = fkey(xv.y); key[2] = fkey(xv.z); key[3] = fkey(xv.w);
        // histogram: warp-aggregated global RED per slot
        #pragma unroll
        for (int s = 0; s < 4; s++) {
            unsigned int b = inb ? (key[s] >> 21) : 0xFFFFFFFFu;
            unsigned int mk = __match_any_sync(0xFFFFFFFFu, b);
            if (b != 0xFFFFFFFFu && lane == (__ffs(mk) - 1))
                atomicAdd(&g_hist[n][b], (unsigned)__popc(mk));
        }
        // prefilter append (k >= STATIC_KEY), one atomic per warp
        int hm = 0;
        if (inb) {
            #pragma unroll
            for (int s = 0; s < 4; s++) hm |= (key[s] >= STATIC_KEY) << s;
        }
        if (__any_sync(0xFFFFFFFFu, hm)) {
            int cnt = __popc(hm);
            int pre = cnt;
            #pragma unroll
            for (int o = 1; o < 32; o <<= 1) {
                int t = __shfl_up_sync(0xFFFFFFFFu, pre, o);
                if (lane >= o) pre += t;
            }
            int total = __shfl_sync(0xFFFFFFFFu, pre, 31);
            unsigned int base = 0;
            if (lane == 31) base = atomicAdd(&g_pcnt[n], (unsigned)total);
            base = __shfl_sync(0xFFFFFFFFu, base, 31);
            unsigned int off = base + (unsigned)(pre - cnt);
            int r = 0;
            #pragma unroll
            for (int s = 0; s < 4; s++) {
                if (hm & (1 << s)) {
                    unsigned int p = off + r++;
                    if (p < GCAND) {
                        int j = (blockIdx.x * 1024 + it * 256 + threadIdx.x) * 4 + s;
                        g_pre[n][p] = ((unsigned long long)key[s] << 32)
                                    | (unsigned int)(~refidx(j));
                    }
                }
            }
        }
    }
}

// ---- kernel 2: pick coarse threshold T1 (with tie-safety margin) -----------
__global__ __launch_bounds__(1024) void pick_kernel() {
    const int n = blockIdx.x, tid = threadIdx.x;
    __shared__ unsigned int hist[2048];
    __shared__ unsigned int s_b1;
    hist[tid] = g_hist[n][tid];
    hist[tid + 1024] = g_hist[n][tid + 1024];
    g_hist[n][tid] = 0;                                  // self-reset for next replay
    g_hist[n][tid + 1024] = 0;
    __syncthreads();
    for (int off = 1; off < 2048; off <<= 1) {
        unsigned a0 = hist[tid]        + ((tid + off < 2048)        ? hist[tid + off]        : 0u);
        unsigned a1 = hist[tid + 1024] + ((tid + 1024 + off < 2048) ? hist[tid + 1024 + off] : 0u);
        __syncthreads();
        hist[tid] = a0; hist[tid + 1024] = a1;
        __syncthreads();
    }
    #pragma unroll
    for (int q = 0; q < 2; q++) {
        int idx = tid + q * 1024;
        unsigned s = hist[idx];
        unsigned snx = (idx < 2047) ? hist[idx + 1] : 0u;
        if (s >= PRE && snx < PRE) s_b1 = (unsigned)idx;
    }
    __syncthreads();
    if (tid == 0) {
        unsigned b1 = s_b1;
        g_T1[n] = (b1 >= 1u) ? ((b1 << 21) - 65536u) : 0u;   // margin >> sigmoid plateau width
    }
}

// ---- kernel 3: refine + sigmoid-key convert + sort + decode + compact ------
__global__ __launch_bounds__(1024) void sortdecode_kernel(const float* __restrict__ obj,
                                                          const float* __restrict__ deltas)
{
    const int n = blockIdx.x;
    const int tid = threadIdx.x;
    const float* ob = obj + (size_t)n * HWA;
    const float* dl = deltas + (size_t)n * HWA * 4;

    __shared__ unsigned int hist[2048];
    __shared__ unsigned long long cand[SCAND];
    __shared__ unsigned int s_b2, s_nc2;

    const unsigned int T1 = g_T1[n];
    unsigned int pcnt = g_pcnt[n];
    const bool fast = (T1 >= STATIC_KEY) && (pcnt <= GCAND);
    if (pcnt > GCAND) pcnt = GCAND;
    if (tid == 0) s_nc2 = 0;
    hist[tid] = 0; hist[tid + 1024] = 0;
    __syncthreads();

    // refine histogram over next 11 key bits (logit space; cap = everything above)
    if (fast) {
        for (unsigned int p = tid; p < pcnt; p += 1024) {
            unsigned int k = (unsigned int)(g_pre[n][p] >> 32);
            if (k >= T1) atomicAdd(&hist[min((k - T1) >> 10, 2047u)], 1u);
        }
    } else {
        for (int j = tid; j < HWA; j += 1024) {         // cold fallback: full rescan
            unsigned int k = fkey(ob[j]);
            if (k >= T1) atomicAdd(&hist[min((k - T1) >> 10, 2047u)], 1u);
        }
    }
    __syncthreads();
    for (int off = 1; off < 2048; off <<= 1) {
        unsigned a0 = hist[tid]        + ((tid + off < 2048)        ? hist[tid + off]        : 0u);
        unsigned a1 = hist[tid + 1024] + ((tid + 1024 + off < 2048) ? hist[tid + 1024 + off] : 0u);
        __syncthreads();
        hist[tid] = a0; hist[tid + 1024] = a1;
        __syncthreads();
    }
    #pragma unroll
    for (int q = 0; q < 2; q++) {
        int idx = tid + q * 1024;
        unsigned s = hist[idx];
        unsigned snx = (idx < 2047) ? hist[idx + 1] : 0u;
        if (s >= PRE && snx < PRE) s_b2 = (unsigned)idx;
    }
    __syncthreads();
    unsigned int B = T1 + (s_b2 << 10);
    const unsigned int Bm = (B >= 256u) ? (B - 256u) : 0u;   // tie-safety margin

    // gather superset, converting logit key -> exact sigmoid key (bit-match XLA)
    if (fast) {
        for (unsigned int p = tid; p < pcnt; p += 1024) {
            unsigned long long c = g_pre[n][p];
            unsigned int k = (unsigned int)(c >> 32);
            if (k >= Bm) {
                float x = funkey(k);
                float s = __fdiv_rn(1.0f, __fadd_rn(1.0f, expf(-x)));
                unsigned int q2 = atomicAdd(&s_nc2, 1u);
                if (q2 < SCAND)
                    cand[q2] = ((unsigned long long)fkey(s) << 32) | (unsigned int)c;
            }
        }
    } else {
        for (int j = tid; j < HWA; j += 1024) {
            float x = ob[j];
            unsigned int k = fkey(x);
            if (k >= Bm) {
                float s = __fdiv_rn(1.0f, __fadd_rn(1.0f, expf(-x)));
                unsigned int q2 = atomicAdd(&s_nc2, 1u);
                if (q2 < SCAND)
                    cand[q2] = ((unsigned long long)fkey(s) << 32) | (unsigned int)(~refidx(j));
            }
        }
    }
    __syncthreads();
    unsigned int nc2 = s_nc2; if (nc2 > SCAND) nc2 = SCAND;
    const int ssz = (nc2 <= 2048) ? 2048 : SCAND;           // usually 2048: cheaper sort
    for (unsigned int p = nc2 + tid; p < (unsigned)ssz; p += 1024) cand[p] = 0ull;
    __syncthreads();

    // bitonic sort, descending composite (sigmoid-bits desc, index asc)
    for (int len = 2; len <= ssz; len <<= 1) {
        for (int stride = len >> 1; stride > 0; stride >>= 1) {
            for (int v = tid; v < ssz / 2; v += 1024) {
                int low = v & (stride - 1);
                int pos = ((v ^ low) << 1) | low;
                int par = pos + stride;
                unsigned long long a = cand[pos], b = cand[par];
                bool desc = ((pos & len) == 0);
                if (desc ? (a < b) : (a > b)) { cand[pos] = b; cand[par] = a; }
            }
            __syncthreads();
        }
    }

    // decode top PRE, clip, min-size filter
    float bxv[2][4]; float scv[2]; unsigned validq[2];
    #pragma unroll
    for (int q = 0; q < 2; q++) {
        int r = tid + q * 1024;
        validq[q] = 0;
        if (r < PRE) {
            unsigned long long c = cand[r];
            unsigned int k = (unsigned int)(c >> 32);
            unsigned int i = ~((unsigned int)c);
            scv[q] = funkey(k);                        // exact sigmoid bits
            int a = (int)(i % AANCH);
            int cell = (int)(i / AANCH);
            int x = cell % WW, y = cell / WW;
            int rIdx = a / 5, sIdx = a % 5;
            float hr = sqrtf(c_ratios[rIdx]);
            float wr = __fdiv_rn(1.0f, hr);
            float wss = __fmul_rn(wr, c_sizes[sIdx]);
            float hss = __fmul_rn(hr, c_sizes[sIdx]);
            float bx1 = rintf(-0.5f * wss), bx2 = rintf(0.5f * wss);
            float by1 = rintf(-0.5f * hss), by2 = rintf(0.5f * hss);
            float ax1 = x * 16.f + bx1, ax2 = x * 16.f + bx2;
            float ay1 = y * 16.f + by1, ay2 = y * 16.f + by2;
            float wa = ax2 - ax1, ha = ay2 - ay1;      // exact integers
            float cxa = ax1 + 0.5f * wa, cya = ay1 + 0.5f * ha;
            float ddx = dl[(a * 4 + 0) * HW + cell];
            float ddy = dl[(a * 4 + 1) * HW + cell];
            float ddw = fminf(dl[(a * 4 + 2) * HW + cell], 4.1351665567423563f);
            float ddh = fminf(dl[(a * 4 + 3) * HW + cell], 4.1351665567423563f);
            float cx = __fadd_rn(__fmul_rn(ddx, wa), cxa);
            float cy = __fadd_rn(__fmul_rn(ddy, ha), cya);
            float w  = __fmul_rn(expf(ddw), wa);
            float h  = __fmul_rn(expf(ddh), ha);
            float x1 = __fsub_rn(cx, __fmul_rn(0.5f, w));
            float y1 = __fsub_rn(cy, __fmul_rn(0.5f, h));
            float x2 = __fadd_rn(cx, __fmul_rn(0.5f, w));
            float y2 = __fadd_rn(cy, __fmul_rn(0.5f, h));
            x1 = fminf(fmaxf(x1, 0.f), 1600.f);
            y1 = fminf(fmaxf(y1, 0.f), 1600.f);
            x2 = fminf(fmaxf(x2, 0.f), 1600.f);
            y2 = fminf(fmaxf(y2, 0.f), 1600.f);
            bxv[q][0] = x1; bxv[q][1] = y1; bxv[q][2] = x2; bxv[q][3] = y2;
            validq[q] = (__fsub_rn(x2, x1) >= 1e-3f) && (__fsub_rn(y2, y1) >= 1e-3f);
        }
    }
    __syncthreads();
    // parallel prefix sum of valid flags
    hist[tid] = (tid < PRE) ? validq[0] : 0u;
    hist[tid + 1024] = (tid + 1024 < PRE) ? validq[1] : 0u;
    __syncthreads();
    for (int off = 1; off < 2048; off <<= 1) {
        unsigned a0 = hist[tid]        + ((tid >= off)        ? hist[tid - off]        : 0u);
        unsigned a1 = hist[tid + 1024] + ((tid + 1024 >= off) ? hist[tid + 1024 - off] : 0u);
        __syncthreads();
        hist[tid] = a0; hist[tid + 1024] = a1;
        __syncthreads();
    }
    if (tid == 0) { g_cnt[n] = (int)hist[PRE - 1]; g_pcnt[n] = 0; }   // + self-reset
    #pragma unroll
    for (int q = 0; q < 2; q++) {
        int r = tid + q * 1024;
        if (r < PRE && validq[q]) {
            int p = (int)hist[r] - 1;
            g_boxes[n][p][0] = bxv[q][0];
            g_boxes[n][p][1] = bxv[q][1];
            g_boxes[n][p][2] = bxv[q][2];
            g_boxes[n][p][3] = bxv[q][3];
            g_scores[n][p]   = scv[q];
        }
    }
}

// ---------------- kernel B: IoU suppression bitmask (upper-tri words only) --
__global__ __launch_bounds__(256) void iou_kernel() {
    const int n = blockIdx.z, bi = blockIdx.y, bj = blockIdx.x;
    if (bi * 4 > bj) return;                            // whole block below diagonal
    const int V = g_cnt[n];
    __shared__ float4 cb[64];
    __shared__ float ca[64];
    const int j0 = bj * 64;
    const int t = threadIdx.x;
    if (t < 64) {
        int j = j0 + t;
        float4 b = make_float4(0.f, 0.f, 0.f, 0.f);
        if (j < V) b = *reinterpret_cast<const float4*>(g_boxes[n][j]);
        cb[t] = b;
        ca[t] = __fmul_rn(__fsub_rn(b.z, b.x), __fsub_rn(b.w, b.y));
    }
    __syncthreads();
    const int i = bi * 256 + t;
    if (i >= 64 * (bj + 1)) return;                     // word below this row's diagonal
    unsigned long long m = 0ull;
    if (i < V && j0 < V && j0 + 63 > i) {
        float4 bb = *reinterpret_cast<const float4*>(g_boxes[n][i]);
        float ai = __fmul_rn(__fsub_rn(bb.z, bb.x), __fsub_rn(bb.w, bb.y));
        int tmax = min(64, V - j0);
        for (int u = 0; u < tmax; u++) {
            int j = j0 + u;
            if (j <= i) continue;
            float4 cc = cb[u];
            float xx1 = fmaxf(bb.x, cc.x), yy1 = fmaxf(bb.y, cc.y);
            float xx2 = fminf(bb.z, cc.z), yy2 = fminf(bb.w, cc.w);
            float iw = fmaxf(__fsub_rn(xx2, xx1), 0.f);
            float ih = fmaxf(__fsub_rn(yy2, yy1), 0.f);
            float inter = __fmul_rn(iw, ih);
            float den = __fadd_rn(__fsub_rn(__fadd_rn(ai, ca[u]), inter), 1e-6f);
            float thr = __fmul_rn(0.7f, den);
            bool sup;
            if (fabsf(__fsub_rn(inter, thr)) > 1e-4f * den)
                sup = inter > thr;                      // decision identical outside margin
            else
                sup = __fdiv_rn(inter, den) > 0.7f;     // exact fallback (rare)
            if (sup) m |= (1ull << u);
        }
    }
    g_mask[n][i][bj] = m;
}

// ---------------- kernel C: greedy NMS, column-on-demand + early exit -------
__global__ __launch_bounds__(256) void nms_kernel(float* __restrict__ out) {
    const int n = blockIdx.x;
    const int tid = threadIdx.x;
    const int lane = tid & 31, wid = tid >> 5;
    const int V = g_cnt[n];
    const int nblk = (V + 63) >> 6;                    // <= 32

    __shared__ unsigned long long skeep[32];
    __shared__ unsigned long long sdiag[64];
    __shared__ unsigned long long swarp[8];
    __shared__ int spfx[33];
    __shared__ int s_kc;

    if (tid < 32) skeep[tid] = 0ull;
    if (tid == 0) s_kc = 0;
    __syncthreads();

    for (int w = 0; w < nblk; w++) {
        const int base = w << 6;
        if (tid < 64) sdiag[tid] = g_mask[n][base + tid][w];
        unsigned long long part = 0ull;
        for (int r = tid; r < base; r += 256) {
            unsigned long long km = skeep[r >> 6];
            unsigned long long sel = 0ull - ((km >> (r & 63)) & 1ull);
            part |= g_mask[n][r][w] & sel;
        }
        #pragma unroll
        for (int o = 16; o > 0; o >>= 1)
            part |= __shfl_xor_sync(0xFFFFFFFFu, part, o);
        if (lane == 0) swarp[wid] = part;
        __syncthreads();

        if (tid == 0) {
            unsigned long long remw = swarp[0] | swarp[1] | swarp[2] | swarp[3]
                                    | swarp[4] | swarp[5] | swarp[6] | swarp[7];
            unsigned long long keep = 0ull;
            #pragma unroll
            for (int u = 0; u < 64; u++) {
                unsigned long long bc =
                    (unsigned long long)(((long long)(remw << (63 - u))) >> 63);
                keep |= ~bc & (1ull << u);
                remw |= sdiag[u] & ~bc;
            }
            int lim = V - base;
            if (lim < 64) keep &= (1ull << lim) - 1ull;
            skeep[w] = keep;
            s_kc += __popcll(keep);
        }
        __syncthreads();
        if (s_kc >= POST) break;
    }

    if (tid == 0) {
        int c = 0;
        #pragma unroll
        for (int p = 0; p < 32; p++) { spfx[p] = c; c += __popcll(skeep[p]); }
        spfx[32] = c;
    }
    __syncthreads();

    float* po = out + (size_t)n * POST * 5;
    const int oc = min(spfx[32], POST);
    for (int i = tid; i < V; i += 256) {
        unsigned long long km = skeep[i >> 6];
        if ((km >> (i & 63)) & 1ull) {
            int rank = spfx[i >> 6] + __popcll(km & ((1ull << (i & 63)) - 1ull));
            if (rank < POST) {
                float4 b = *reinterpret_cast<const float4*>(g_boxes[n][i]);
                po[rank * 5 + 0] = b.x;
                po[rank * 5 + 1] = b.y;
                po[rank * 5 + 2] = b.z;
                po[rank * 5 + 3] = b.w;
                po[rank * 5 + 4] = g_scores[n][i];
            }
        }
    }
    for (int t = oc * 5 + tid; t < POST * 5; t += 256) po[t] = 0.f;
}

// ---------------- launch ----------------------------------------------------
extern "C" void kernel_launch(void* const* d_in, const int* in_sizes, int n_in,
                              void* d_out, int out_size) {
    const float* obj = (const float*)d_in[0];
    const float* dl  = (const float*)d_in[1];
    if (in_sizes[0] != NIMG * HWA) { const float* t = obj; obj = dl; dl = t; }

    dim3 gh(37, NIMG);
    hist_kernel<<<gh, 256>>>(obj);
    pick_kernel<<<NIMG, 1024>>>();
    sortdecode_kernel<<<NIMG, 1024>>>(obj, dl);
    dim3 gb(32, 8, NIMG);
    iou_kernel<<<gb, 256>>>();
    nms_kernel<<<NIMG, 256>>>((float*)d_out);
}

// round 15
// speedup vs baseline: 5.0258x; 1.0649x over previous
#include <cuda_runtime.h>
#include <math.h>

#define NIMG 8
#define AANCH 15
#define WW 100
#define HW 10000
#define HWA 150000
#define NF4 37500
#define PRE 2000
#define POST 1000
#define GCAND 8192
#define SCAND 4096
#define STATIC_KEY 0xBFD9999Au   /* fkey(1.7f): static logit prefilter */

// ---------------- device scratch (static, no runtime alloc) ----------------
__device__ __align__(16) float g_boxes[NIMG][2048][4];              // compacted valid boxes, score order
__device__ float g_scores[NIMG][2048];
__device__ int   g_cnt[NIMG];                                       // V = #valid per image
__device__ unsigned long long g_mask[NIMG][2048][32];               // suppression bitmask rows
__device__ unsigned int g_hist[NIMG][2048];                         // level-1 logit-key histogram (self-reset)
__device__ unsigned int g_pcnt[NIMG];                               // prefilter counters (self-reset)
__device__ unsigned long long g_pre[NIMG][GCAND];                   // prefilter list: xkey<<32 | ~refIdx

__constant__ float c_sizes[5]  = {32.f, 64.f, 128.f, 256.f, 512.f};
__constant__ float c_ratios[3] = {0.5f, 1.f, 2.f};

// monotone float<->uint key (larger float <-> larger key)
__device__ __forceinline__ unsigned int fkey(float f) {
    unsigned int u = __float_as_uint(f);
    return (u & 0x80000000u) ? ~u : (u | 0x80000000u);
}
__device__ __forceinline__ float funkey(unsigned int k) {
    unsigned int u = (k & 0x80000000u) ? (k ^ 0x80000000u) : ~k;
    return __uint_as_float(u);
}
__device__ __forceinline__ unsigned int refidx(int j) {             // input-layout j -> reference HWA index
    return (unsigned)((j % HW) * AANCH + j / HW);
}

// margin-guarded IoU>0.7 decision, bit-identical to reference div compare
__device__ __forceinline__ unsigned long long ioubit(const float4& bb, float ai,
                                                     const float4& cc, float aj) {
    float xx1 = fmaxf(bb.x, cc.x), yy1 = fmaxf(bb.y, cc.y);
    float xx2 = fminf(bb.z, cc.z), yy2 = fminf(bb.w, cc.w);
    float iw = fmaxf(__fsub_rn(xx2, xx1), 0.f);
    float ih = fmaxf(__fsub_rn(yy2, yy1), 0.f);
    float inter = __fmul_rn(iw, ih);
    float den = __fadd_rn(__fsub_rn(__fadd_rn(ai, aj), inter), 1e-6f);
    float thr = __fmul_rn(0.7f, den);
    bool sup;
    if (fabsf(__fsub_rn(inter, thr)) > 1e-4f * den)
        sup = inter > thr;                        // decision identical outside margin
    else
        sup = __fdiv_rn(inter, den) > 0.7f;       // exact fallback (rare)
    return sup ? 1ull : 0ull;
}

// ---- kernel 1: logit-key histogram + static prefilter append (one pass) ----
__global__ __launch_bounds__(256) void hist_kernel(const float* __restrict__ obj) {
    const int n = blockIdx.y;
    const int lane = threadIdx.x & 31;
    const float4* ob4 = (const float4*)(obj + (size_t)n * HWA);
    unsigned int key[4];
    #pragma unroll
    for (int it = 0; it < 4; it++) {
        int v = blockIdx.x * 1024 + it * 256 + threadIdx.x;
        bool inb = v < NF4;
        float4 xv = make_float4(0.f, 0.f, 0.f, 0.f);
        if (inb) xv = ob4[v];
        key[0] = fkey(xv.x); key[1] = fkey(xv.y); key[2] = fkey(xv.z); key[3] = fkey(xv.w);
        #pragma unroll
        for (int s = 0; s < 4; s++) {
            unsigned int b = inb ? (key[s] >> 21) : 0xFFFFFFFFu;
            unsigned int mk = __match_any_sync(0xFFFFFFFFu, b);
            if (b != 0xFFFFFFFFu && lane == (__ffs(mk) - 1))
                atomicAdd(&g_hist[n][b], (unsigned)__popc(mk));
        }
        int hm = 0;
        if (inb) {
            #pragma unroll
            for (int s = 0; s < 4; s++) hm |= (key[s] >= STATIC_KEY) << s;
        }
        if (__any_sync(0xFFFFFFFFu, hm)) {
            int cnt = __popc(hm);
            int pre = cnt;
            #pragma unroll
            for (int o = 1; o < 32; o <<= 1) {
                int t = __shfl_up_sync(0xFFFFFFFFu, pre, o);
                if (lane >= o) pre += t;
            }
            int total = __shfl_sync(0xFFFFFFFFu, pre, 31);
            unsigned int base = 0;
            if (lane == 31) base = atomicAdd(&g_pcnt[n], (unsigned)total);
            base = __shfl_sync(0xFFFFFFFFu, base, 31);
            unsigned int off = base + (unsigned)(pre - cnt);
            int r = 0;
            #pragma unroll
            for (int s = 0; s < 4; s++) {
                if (hm & (1 << s)) {
                    unsigned int p = off + r++;
                    if (p < GCAND) {
                        int j = (blockIdx.x * 1024 + it * 256 + threadIdx.x) * 4 + s;
                        g_pre[n][p] = ((unsigned long long)key[s] << 32)
                                    | (unsigned int)(~refidx(j));
                    }
                }
            }
        }
    }
}

// ---- kernel 2: pick + refine + sigmoid convert + sort + decode + compact ---
__global__ __launch_bounds__(1024) void sortdecode_kernel(const float* __restrict__ obj,
                                                          const float* __restrict__ deltas)
{
    const int n = blockIdx.x;
    const int tid = threadIdx.x;
    const float* ob = obj + (size_t)n * HWA;
    const float* dl = deltas + (size_t)n * HWA * 4;

    __shared__ unsigned int hist[2048];
    __shared__ unsigned long long cand[SCAND];
    __shared__ unsigned int s_b1, s_b2, s_nc2;

    // ---- pick: level-1 suffix scan over global histogram (+ self-reset) ----
    hist[tid] = g_hist[n][tid];
    hist[tid + 1024] = g_hist[n][tid + 1024];
    g_hist[n][tid] = 0;
    g_hist[n][tid + 1024] = 0;
    __syncthreads();
    for (int off = 1; off < 2048; off <<= 1) {
        unsigned a0 = hist[tid]        + ((tid + off < 2048)        ? hist[tid + off]        : 0u);
        unsigned a1 = hist[tid + 1024] + ((tid + 1024 + off < 2048) ? hist[tid + 1024 + off] : 0u);
        __syncthreads();
        hist[tid] = a0; hist[tid + 1024] = a1;
        __syncthreads();
    }
    #pragma unroll
    for (int q = 0; q < 2; q++) {
        int idx = tid + q * 1024;
        unsigned s = hist[idx];
        unsigned snx = (idx < 2047) ? hist[idx + 1] : 0u;
        if (s >= PRE && snx < PRE) s_b1 = (unsigned)idx;
    }
    __syncthreads();
    // margin (2^16 key ulps in logit space) >> sigmoid-tie plateau width
    const unsigned int T1 = (s_b1 >= 1u) ? ((s_b1 << 21) - 65536u) : 0u;

    unsigned int pcnt = g_pcnt[n];
    const bool fast = (T1 >= STATIC_KEY) && (pcnt <= GCAND);
    if (pcnt > GCAND) pcnt = GCAND;
    if (tid == 0) s_nc2 = 0;
    hist[tid] = 0; hist[tid + 1024] = 0;
    __syncthreads();

    // refine histogram over next 11 key bits (logit space; cap = everything above)
    if (fast) {
        for (unsigned int p = tid; p < pcnt; p += 1024) {
            unsigned int k = (unsigned int)(g_pre[n][p] >> 32);
            if (k >= T1) atomicAdd(&hist[min((k - T1) >> 10, 2047u)], 1u);
        }
    } else {
        for (int j = tid; j < HWA; j += 1024) {         // cold fallback: full rescan
            unsigned int k = fkey(ob[j]);
            if (k >= T1) atomicAdd(&hist[min((k - T1) >> 10, 2047u)], 1u);
        }
    }
    __syncthreads();
    for (int off = 1; off < 2048; off <<= 1) {
        unsigned a0 = hist[tid]        + ((tid + off < 2048)        ? hist[tid + off]        : 0u);
        unsigned a1 = hist[tid + 1024] + ((tid + 1024 + off < 2048) ? hist[tid + 1024 + off] : 0u);
        __syncthreads();
        hist[tid] = a0; hist[tid + 1024] = a1;
        __syncthreads();
    }
    #pragma unroll
    for (int q = 0; q < 2; q++) {
        int idx = tid + q * 1024;
        unsigned s = hist[idx];
        unsigned snx = (idx < 2047) ? hist[idx + 1] : 0u;
        if (s >= PRE && snx < PRE) s_b2 = (unsigned)idx;
    }
    __syncthreads();
    unsigned int B = T1 + (s_b2 << 10);
    const unsigned int Bm = (B >= 256u) ? (B - 256u) : 0u;   // tie-safety margin

    // gather superset, converting logit key -> exact sigmoid key (bit-match XLA)
    if (fast) {
        for (unsigned int p = tid; p < pcnt; p += 1024) {
            unsigned long long c = g_pre[n][p];
            unsigned int k = (unsigned int)(c >> 32);
            if (k >= Bm) {
                float x = funkey(k);
                float s = __fdiv_rn(1.0f, __fadd_rn(1.0f, expf(-x)));
                unsigned int q2 = atomicAdd(&s_nc2, 1u);
                if (q2 < SCAND)
                    cand[q2] = ((unsigned long long)fkey(s) << 32) | (unsigned int)c;
            }
        }
    } else {
        for (int j = tid; j < HWA; j += 1024) {
            float x = ob[j];
            unsigned int k = fkey(x);
            if (k >= Bm) {
                float s = __fdiv_rn(1.0f, __fadd_rn(1.0f, expf(-x)));
                unsigned int q2 = atomicAdd(&s_nc2, 1u);
                if (q2 < SCAND)
                    cand[q2] = ((unsigned long long)fkey(s) << 32) | (unsigned int)(~refidx(j));
            }
        }
    }
    __syncthreads();
    unsigned int nc2 = s_nc2; if (nc2 > SCAND) nc2 = SCAND;
    const int ssz = (nc2 <= 2048) ? 2048 : SCAND;           // usually 2048: cheaper sort
    for (unsigned int p = nc2 + tid; p < (unsigned)ssz; p += 1024) cand[p] = 0ull;
    __syncthreads();

    // bitonic sort, descending composite (sigmoid-bits desc, index asc)
    for (int len = 2; len <= ssz; len <<= 1) {
        for (int stride = len >> 1; stride > 0; stride >>= 1) {
            for (int v = tid; v < ssz / 2; v += 1024) {
                int low = v & (stride - 1);
                int pos = ((v ^ low) << 1) | low;
                int par = pos + stride;
                unsigned long long a = cand[pos], b = cand[par];
                bool desc = ((pos & len) == 0);
                if (desc ? (a < b) : (a > b)) { cand[pos] = b; cand[par] = a; }
            }
            __syncthreads();
        }
    }

    // decode top PRE, clip, min-size filter
    float bxv[2][4]; float scv[2]; unsigned validq[2];
    #pragma unroll
    for (int q = 0; q < 2; q++) {
        int r = tid + q * 1024;
        validq[q] = 0;
        if (r < PRE) {
            unsigned long long c = cand[r];
            unsigned int k = (unsigned int)(c >> 32);
            unsigned int i = ~((unsigned int)c);
            scv[q] = funkey(k);                        // exact sigmoid bits
            int a = (int)(i % AANCH);
            int cell = (int)(i / AANCH);
            int x = cell % WW, y = cell / WW;
            int rIdx = a / 5, sIdx = a % 5;
            float hr = sqrtf(c_ratios[rIdx]);
            float wr = __fdiv_rn(1.0f, hr);
            float wss = __fmul_rn(wr, c_sizes[sIdx]);
            float hss = __fmul_rn(hr, c_sizes[sIdx]);
            float bx1 = rintf(-0.5f * wss), bx2 = rintf(0.5f * wss);
            float by1 = rintf(-0.5f * hss), by2 = rintf(0.5f * hss);
            float ax1 = x * 16.f + bx1, ax2 = x * 16.f + bx2;
            float ay1 = y * 16.f + by1, ay2 = y * 16.f + by2;
            float wa = ax2 - ax1, ha = ay2 - ay1;      // exact integers
            float cxa = ax1 + 0.5f * wa, cya = ay1 + 0.5f * ha;
            float ddx = dl[(a * 4 + 0) * HW + cell];
            float ddy = dl[(a * 4 + 1) * HW + cell];
            float ddw = fminf(dl[(a * 4 + 2) * HW + cell], 4.1351665567423563f);
            float ddh = fminf(dl[(a * 4 + 3) * HW + cell], 4.1351665567423563f);
            float cx = __fadd_rn(__fmul_rn(ddx, wa), cxa);
            float cy = __fadd_rn(__fmul_rn(ddy, ha), cya);
            float w  = __fmul_rn(expf(ddw), wa);
            float h  = __fmul_rn(expf(ddh), ha);
            float x1 = __fsub_rn(cx, __fmul_rn(0.5f, w));
            float y1 = __fsub_rn(cy, __fmul_rn(0.5f, h));
            float x2 = __fadd_rn(cx, __fmul_rn(0.5f, w));
            float y2 = __fadd_rn(cy, __fmul_rn(0.5f, h));
            x1 = fminf(fmaxf(x1, 0.f), 1600.f);
            y1 = fminf(fmaxf(y1, 0.f), 1600.f);
            x2 = fminf(fmaxf(x2, 0.f), 1600.f);
            y2 = fminf(fmaxf(y2, 0.f), 1600.f);
            bxv[q][0] = x1; bxv[q][1] = y1; bxv[q][2] = x2; bxv[q][3] = y2;
            validq[q] = (__fsub_rn(x2, x1) >= 1e-3f) && (__fsub_rn(y2, y1) >= 1e-3f);
        }
    }
    __syncthreads();
    // parallel prefix sum of valid flags
    hist[tid] = (tid < PRE) ? validq[0] : 0u;
    hist[tid + 1024] = (tid + 1024 < PRE) ? validq[1] : 0u;
    __syncthreads();
    for (int off = 1; off < 2048; off <<= 1) {
        unsigned a0 = hist[tid]        + ((tid >= off)        ? hist[tid - off]        : 0u);
        unsigned a1 = hist[tid + 1024] + ((tid + 1024 >= off) ? hist[tid + 1024 - off] : 0u);
        __syncthreads();
        hist[tid] = a0; hist[tid + 1024] = a1;
        __syncthreads();
    }
    if (tid == 0) { g_cnt[n] = (int)hist[PRE - 1]; g_pcnt[n] = 0; }   // + self-reset
    #pragma unroll
    for (int q = 0; q < 2; q++) {
        int r = tid + q * 1024;
        if (r < PRE && validq[q]) {
            int p = (int)hist[r] - 1;
            g_boxes[n][p][0] = bxv[q][0];
            g_boxes[n][p][1] = bxv[q][1];
            g_boxes[n][p][2] = bxv[q][2];
            g_boxes[n][p][3] = bxv[q][3];
            g_scores[n][p]   = scv[q];
        }
    }
}

// ---- kernel B: IoU bitmask, 2 rows/thread, branchless inner loop -----------
// Thread handles rows i0 = bi*256+t and i1 = i0+128 against col word bj.
// All 64 pair bits computed unconditionally; invalid bits (j<=i, j>=V) are
// cleared by post-loop masks. Geometry: if i0 lies in the diagonal word, i1's
// word-bj mask is below i1's diagonal (never read), so no conflict.
__global__ __launch_bounds__(128) void iou_kernel() {
    const int n = blockIdx.z, bi = blockIdx.y, bj = blockIdx.x;
    if (bi * 4 > bj) return;                            // whole 256-row stripe below diagonal
    const int V = g_cnt[n];
    __shared__ float4 cb[64];
    __shared__ float ca[64];
    const int j0 = bj * 64;
    const int t = threadIdx.x;
    if (t < 64) {
        int j = j0 + t;
        float4 b = make_float4(0.f, 0.f, 0.f, 0.f);
        if (j < V) b = *reinterpret_cast<const float4*>(g_boxes[n][j]);
        cb[t] = b;
        ca[t] = __fmul_rn(__fsub_rn(b.z, b.x), __fsub_rn(b.w, b.y));
    }
    __syncthreads();

    const int i0 = bi * 256 + t;
    const int i1 = i0 + 128;
    const int dlim = 64 * (bj + 1);
    const bool w0 = (i0 < dlim);                        // word needed for row
    const bool w1 = (i1 < dlim);
    if (!w0 && !w1) return;

    float4 bb0 = *reinterpret_cast<const float4*>(g_boxes[n][i0]);
    float4 bb1 = *reinterpret_cast<const float4*>(g_boxes[n][i1]);
    float ai0 = __fmul_rn(__fsub_rn(bb0.z, bb0.x), __fsub_rn(bb0.w, bb0.y));
    float ai1 = __fmul_rn(__fsub_rn(bb1.z, bb1.x), __fsub_rn(bb1.w, bb1.y));

    unsigned long long m0 = 0ull, m1 = 0ull;
    #pragma unroll 8
    for (int u = 0; u < 64; u++) {
        float4 cc = cb[u];
        float aj = ca[u];
        m0 |= ioubit(bb0, ai0, cc, aj) << u;
        m1 |= ioubit(bb1, ai1, cc, aj) << u;
    }

    // clear j >= V bits
    int tm = V - j0;
    if (tm <= 0) { m0 = 0ull; m1 = 0ull; }
    else if (tm < 64) { unsigned long long hi = (1ull << tm) - 1ull; m0 &= hi; m1 &= hi; }
    // clear j <= i bits (d in [0,63] when row intersects/below this word start)
    int d0 = i0 - j0;
    if (d0 >= 0) m0 &= ~((2ull << d0) - 1ull);
    int d1 = i1 - j0;
    if (d1 >= 0) m1 &= ~((2ull << d1) - 1ull);

    if (w0) g_mask[n][i0][bj] = m0;
    if (w1) g_mask[n][i1][bj] = m1;
}

// ---------------- kernel C: greedy NMS, column-on-demand + early exit -------
__global__ __launch_bounds__(256) void nms_kernel(float* __restrict__ out) {
    const int n = blockIdx.x;
    const int tid = threadIdx.x;
    const int lane = tid & 31, wid = tid >> 5;
    const int V = g_cnt[n];
    const int nblk = (V + 63) >> 6;                    // <= 32

    __shared__ unsigned long long skeep[32];
    __shared__ unsigned long long sdiag[64];
    __shared__ unsigned long long swarp[8];
    __shared__ int spfx[33];
    __shared__ int s_kc;

    if (tid < 32) skeep[tid] = 0ull;
    if (tid == 0) s_kc = 0;
    __syncthreads();

    for (int w = 0; w < nblk; w++) {
        const int base = w << 6;
        if (tid < 64) sdiag[tid] = g_mask[n][base + tid][w];
        unsigned long long part = 0ull;
        for (int r = tid; r < base; r += 256) {
            unsigned long long km = skeep[r >> 6];
            unsigned long long sel = 0ull - ((km >> (r & 63)) & 1ull);
            part |= g_mask[n][r][w] & sel;
        }
        #pragma unroll
        for (int o = 16; o > 0; o >>= 1)
            part |= __shfl_xor_sync(0xFFFFFFFFu, part, o);
        if (lane == 0) swarp[wid] = part;
        __syncthreads();

        if (tid == 0) {
            unsigned long long remw = swarp[0] | swarp[1] | swarp[2] | swarp[3]
                                    | swarp[4] | swarp[5] | swarp[6] | swarp[7];
            unsigned long long keep = 0ull;
            #pragma unroll
            for (int u = 0; u < 64; u++) {
                unsigned long long bc =
                    (unsigned long long)(((long long)(remw << (63 - u))) >> 63);
                keep |= ~bc & (1ull << u);
                remw |= sdiag[u] & ~bc;
            }
            int lim = V - base;
            if (lim < 64) keep &= (1ull << lim) - 1ull;
            skeep[w] = keep;
            s_kc += __popcll(keep);
        }
        __syncthreads();
        if (s_kc >= POST) break;
    }

    if (tid == 0) {
        int c = 0;
        #pragma unroll
        for (int p = 0; p < 32; p++) { spfx[p] = c; c += __popcll(skeep[p]); }
        spfx[32] = c;
    }
    __syncthreads();

    float* po = out + (size_t)n * POST * 5;
    const int oc = min(spfx[32], POST);
    for (int i = tid; i < V; i += 256) {
        unsigned long long km = skeep[i >> 6];
        if ((km >> (i & 63)) & 1ull) {
            int rank = spfx[i >> 6] + __popcll(km & ((1ull << (i & 63)) - 1ull));
            if (rank < POST) {
                float4 b = *reinterpret_cast<const float4*>(g_boxes[n][i]);
                po[rank * 5 + 0] = b.x;
                po[rank * 5 + 1] = b.y;
                po[rank * 5 + 2] = b.z;
                po[rank * 5 + 3] = b.w;
                po[rank * 5 + 4] = g_scores[n][i];
            }
        }
    }
    for (int t = oc * 5 + tid; t < POST * 5; t += 256) po[t] = 0.f;
}

// ---------------- launch ----------------------------------------------------
extern "C" void kernel_launch(void* const* d_in, const int* in_sizes, int n_in,
                              void* d_out, int out_size) {
    const float* obj = (const float*)d_in[0];
    const float* dl  = (const float*)d_in[1];
    if (in_sizes[0] != NIMG * HWA) { const float* t = obj; obj = dl; dl = t; }

    dim3 gh(37, NIMG);
    hist_kernel<<<gh, 256>>>(obj);
    sortdecode_kernel<<<NIMG, 1024>>>(obj, dl);
    dim3 gb(32, 8, NIMG);
    iou_kernel<<<gb, 128>>>();
    nms_kernel<<<NIMG, 256>>>((float*)d_out);
}